// round 2
// baseline (speedup 1.0000x reference)
#include <cuda_runtime.h>

// Problem constants (fixed shapes for this problem instance)
#define N_CELL   66
#define N_NODES  30000
#define FDIM     256
#define E_TOT    960000            // directed edges (both directions)
#define NF       (N_NODES * FDIM)  // 7,680,000
#define NF4      (NF / 4)
#define CELL4    ((N_CELL * FDIM) / 4)
#define BN_EPS   1e-5f

// GEMM tiling
#define GBM 128
#define GBN 64
#define GBK 16
#define GMB 235                    // ceil(30000/128)

// ---------------- device scratch (static, no allocation) ----------------
__device__ float g_x0[NF];
__device__ float g_x1[NF];
__device__ float g_deg[N_NODES];
__device__ float g_dinv[N_NODES];
__device__ int   g_count[N_NODES];
__device__ int   g_colptr[N_NODES + 1];
__device__ int   g_cursor[N_NODES];
__device__ int   g_erow[E_TOT];
__device__ float g_enorm[E_TOT];
__device__ float g_gp1[4 * GMB * GBN];   // per-block BN partial sums
__device__ float g_gp2[4 * GMB * GBN];   // per-block BN partial sumsq
__device__ float g_scale[FDIM];
__device__ float g_shift[FDIM];

// ---------------- packed f32x2 helpers ----------------
__device__ __forceinline__ unsigned long long pack2(float lo, float hi) {
    unsigned long long r;
    asm("mov.b64 %0, {%1, %2};" : "=l"(r) : "f"(lo), "f"(hi));
    return r;
}
__device__ __forceinline__ void unpack2(unsigned long long v, float& lo, float& hi) {
    asm("mov.b64 {%0, %1}, %2;" : "=f"(lo), "=f"(hi) : "l"(v));
}
__device__ __forceinline__ void ffma2(unsigned long long& d,
                                      unsigned long long a, unsigned long long b) {
    asm("fma.rn.f32x2 %0, %1, %2, %3;" : "=l"(d) : "l"(a), "l"(b), "l"(d));
}

// ---------------- setup kernels ----------------
__global__ void k_init() {
    int i = blockIdx.x * blockDim.x + threadIdx.x;
    if (i < N_NODES) { g_deg[i] = 1.0f; g_count[i] = 0; }  // self-loop weight = 1
}

__global__ void k_concat(const float4* __restrict__ cell, const float4* __restrict__ sub) {
    int i = blockIdx.x * blockDim.x + threadIdx.x;
    if (i >= NF4) return;
    float4 v = (i < CELL4) ? cell[i] : sub[i - CELL4];
    reinterpret_cast<float4*>(g_x0)[i] = v;
}

__global__ void k_degree(const int* __restrict__ ei, const float* __restrict__ ew) {
    int e = blockIdx.x * blockDim.x + threadIdx.x;
    if (e >= E_TOT) return;
    int c = ei[E_TOT + e];             // target (col)
    atomicAdd(&g_deg[c], ew[e]);
    atomicAdd(&g_count[c], 1);
}

__global__ void k_dinv() {
    int i = blockIdx.x * blockDim.x + threadIdx.x;
    if (i < N_NODES) g_dinv[i] = rsqrtf(g_deg[i]);   // deg >= 1 always
}

// single-block exclusive scan of g_count -> g_colptr / g_cursor
__global__ void k_scan() {
    __shared__ int sums[1024];
    int t = threadIdx.x;
    int base = t * 30;                 // 1024*30 = 30720 >= 30000
    int s = 0;
    for (int i = 0; i < 30; i++) {
        int idx = base + i;
        if (idx < N_NODES) s += g_count[idx];
    }
    sums[t] = s;
    __syncthreads();
    for (int off = 1; off < 1024; off <<= 1) {
        int v = (t >= off) ? sums[t - off] : 0;
        __syncthreads();
        sums[t] += v;
        __syncthreads();
    }
    int run = (t == 0) ? 0 : sums[t - 1];
    for (int i = 0; i < 30; i++) {
        int idx = base + i;
        if (idx < N_NODES) {
            g_colptr[idx] = run;
            g_cursor[idx] = run;
            run += g_count[idx];
        }
    }
    if (t == 1023) g_colptr[N_NODES] = E_TOT;
}

__global__ void k_scatter(const int* __restrict__ ei, const float* __restrict__ ew) {
    int e = blockIdx.x * blockDim.x + threadIdx.x;
    if (e >= E_TOT) return;
    int r = ei[e];
    int c = ei[E_TOT + e];
    int pos = atomicAdd(&g_cursor[c], 1);
    g_erow[pos]  = r;
    g_enorm[pos] = g_dinv[r] * ew[e] * g_dinv[c];
}

// ---------------- SpMM: one block per destination node ----------------
// FOLD: applies pending BN as  out = scale[f]*acc + shift[f]*sum_w  (linearity)
template <bool X0_TO_X1, bool FOLD>
__global__ __launch_bounds__(256) void k_spmm() {
    const float* __restrict__ xin  = X0_TO_X1 ? g_x0 : g_x1;
    float*       __restrict__ xout = X0_TO_X1 ? g_x1 : g_x0;
    int i = blockIdx.x;
    int f = threadIdx.x;
    int beg = g_colptr[i];
    int end = g_colptr[i + 1];
    float di = g_dinv[i];
    float selfw = di * di;
    float acc = selfw * xin[(size_t)i * FDIM + f];   // self-loop term
    float sw  = selfw;
#pragma unroll 4
    for (int e = beg; e < end; e++) {
        int   r = g_erow[e];
        float w = g_enorm[e];
        acc += w * xin[(size_t)r * FDIM + f];
        sw  += w;
    }
    if (FOLD)
        xout[(size_t)i * FDIM + f] = g_scale[f] * acc + g_shift[f] * sw;
    else
        xout[(size_t)i * FDIM + f] = acc;
}

// ---------------- fused GEMM: C = prelu(A @ W^T + b), + BN partial stats ----
// A = g_x1 [N,256] -> C = g_x0.  Packed f32x2 FMA, lanes paired along M.
__global__ __launch_bounds__(256) void k_gemm_fused(const float* __restrict__ W,
                                                    const float* __restrict__ bias,
                                                    const float* __restrict__ pw) {
    __shared__ __align__(16) float As[GBK][GBM];   // k-major, 512B rows
    __shared__ __align__(16) float Bs[GBK][GBN];   // k-major, 256B rows
    __shared__ float Red[16][GBN];

    const float* __restrict__ A = g_x1;
    float* __restrict__ C = g_x0;

    int bm = blockIdx.x * GBM;
    int bn = blockIdx.y * GBN;
    int t  = threadIdx.x;
    int tn  = t & 15;          // n-group (4 cols)
    int tmg = t >> 4;          // m-group (8 rows), 0..15

    // A-tile loader: lm = t&127 row, lk8 = (t>>7)*8 k-offset (8 k per thread)
    int lm  = t & 127;
    int lk8 = (t >> 7) * 8;
    int gm_ld = bm + lm;
    const float* Aptr = A + (size_t)gm_ld * FDIM + lk8;
    // B-tile loader: ln = t&63 row of W, lk4 = (t>>6)*4
    int ln  = t & 63;
    int lk4 = (t >> 6) * 4;
    const float* Wptr = W + (size_t)(bn + ln) * FDIM + lk4;

    unsigned long long acc[4][4];
#pragma unroll
    for (int i = 0; i < 4; i++)
#pragma unroll
        for (int j = 0; j < 4; j++) acc[i][j] = 0ull;

    for (int k0 = 0; k0 < FDIM; k0 += GBK) {
        float4 a0 = make_float4(0.f, 0.f, 0.f, 0.f);
        float4 a1 = make_float4(0.f, 0.f, 0.f, 0.f);
        if (gm_ld < N_NODES) {
            a0 = *reinterpret_cast<const float4*>(Aptr + k0);
            a1 = *reinterpret_cast<const float4*>(Aptr + k0 + 4);
        }
        float4 bv = *reinterpret_cast<const float4*>(Wptr + k0);
        As[lk8 + 0][lm] = a0.x; As[lk8 + 1][lm] = a0.y;
        As[lk8 + 2][lm] = a0.z; As[lk8 + 3][lm] = a0.w;
        As[lk8 + 4][lm] = a1.x; As[lk8 + 5][lm] = a1.y;
        As[lk8 + 6][lm] = a1.z; As[lk8 + 7][lm] = a1.w;
        Bs[lk4 + 0][ln] = bv.x; Bs[lk4 + 1][ln] = bv.y;
        Bs[lk4 + 2][ln] = bv.z; Bs[lk4 + 3][ln] = bv.w;
        __syncthreads();
#pragma unroll
        for (int kk = 0; kk < GBK; kk++) {
            // 4 m-pairs: directly read as packed b64 (adjacent rows)
            ulonglong2 a01 = *reinterpret_cast<const ulonglong2*>(&As[kk][tmg * 8]);
            ulonglong2 a23 = *reinterpret_cast<const ulonglong2*>(&As[kk][tmg * 8 + 4]);
            float4 b = *reinterpret_cast<const float4*>(&Bs[kk][tn * 4]);
            unsigned long long b0 = pack2(b.x, b.x);
            unsigned long long b1 = pack2(b.y, b.y);
            unsigned long long b2 = pack2(b.z, b.z);
            unsigned long long b3 = pack2(b.w, b.w);
            ffma2(acc[0][0], a01.x, b0); ffma2(acc[0][1], a01.x, b1);
            ffma2(acc[0][2], a01.x, b2); ffma2(acc[0][3], a01.x, b3);
            ffma2(acc[1][0], a01.y, b0); ffma2(acc[1][1], a01.y, b1);
            ffma2(acc[1][2], a01.y, b2); ffma2(acc[1][3], a01.y, b3);
            ffma2(acc[2][0], a23.x, b0); ffma2(acc[2][1], a23.x, b1);
            ffma2(acc[2][2], a23.x, b2); ffma2(acc[2][3], a23.x, b3);
            ffma2(acc[3][0], a23.y, b0); ffma2(acc[3][1], a23.y, b1);
            ffma2(acc[3][2], a23.y, b2); ffma2(acc[3][3], a23.y, b3);
        }
        __syncthreads();
    }

    // -------- epilogue: bias + PReLU + store + per-column partial stats ------
    int n0 = bn + tn * 4;
    float4 bb  = *reinterpret_cast<const float4*>(&bias[n0]);
    float4 pwv = *reinterpret_cast<const float4*>(&pw[n0]);
    float cs[4]  = {0.f, 0.f, 0.f, 0.f};
    float cs2[4] = {0.f, 0.f, 0.f, 0.f};
#pragma unroll
    for (int mp = 0; mp < 4; mp++) {
        float v0[4], v1[4];
        unpack2(acc[mp][0], v0[0], v1[0]);
        unpack2(acc[mp][1], v0[1], v1[1]);
        unpack2(acc[mp][2], v0[2], v1[2]);
        unpack2(acc[mp][3], v0[3], v1[3]);
        int m0 = bm + tmg * 8 + mp * 2;
#pragma unroll
        for (int h = 0; h < 2; h++) {
            float* v = h ? v1 : v0;
            int m = m0 + h;
            v[0] += bb.x; v[1] += bb.y; v[2] += bb.z; v[3] += bb.w;
            v[0] = (v[0] >= 0.f) ? v[0] : pwv.x * v[0];
            v[1] = (v[1] >= 0.f) ? v[1] : pwv.y * v[1];
            v[2] = (v[2] >= 0.f) ? v[2] : pwv.z * v[2];
            v[3] = (v[3] >= 0.f) ? v[3] : pwv.w * v[3];
            if (m < N_NODES) {
                *reinterpret_cast<float4*>(&C[(size_t)m * FDIM + n0]) =
                    make_float4(v[0], v[1], v[2], v[3]);
#pragma unroll
                for (int i = 0; i < 4; i++) { cs[i] += v[i]; cs2[i] += v[i] * v[i]; }
            }
        }
    }

    // deterministic in-block column reduction (no atomics)
    int pbase = (blockIdx.y * GMB + blockIdx.x) * GBN;
#pragma unroll
    for (int i = 0; i < 4; i++) Red[tmg][tn * 4 + i] = cs[i];
    __syncthreads();
    if (t < GBN) {
        float s = 0.f;
#pragma unroll
        for (int r = 0; r < 16; r++) s += Red[r][t];
        g_gp1[pbase + t] = s;
    }
    __syncthreads();
#pragma unroll
    for (int i = 0; i < 4; i++) Red[tmg][tn * 4 + i] = cs2[i];
    __syncthreads();
    if (t < GBN) {
        float s = 0.f;
#pragma unroll
        for (int r = 0; r < 16; r++) s += Red[r][t];
        g_gp2[pbase + t] = s;
    }
}

// ---------------- BN finalize: reduce per-block partials -> scale/shift -----
__global__ void k_bn_finalize(const float* __restrict__ gamma,
                              const float* __restrict__ beta) {
    int f  = threadIdx.x;         // 256 threads, 1 block — deterministic order
    int by = f >> 6;
    int c  = f & 63;
    float s = 0.f, s2 = 0.f;
    for (int bx = 0; bx < GMB; bx++) {
        int idx = (by * GMB + bx) * GBN + c;
        s  += g_gp1[idx];
        s2 += g_gp2[idx];
    }
    float inv_n = 1.0f / (float)N_NODES;
    float mean = s * inv_n;
    float var  = s2 * inv_n - mean * mean;
    float sc   = gamma[f] * rsqrtf(var + BN_EPS);
    g_scale[f] = sc;
    g_shift[f] = beta[f] - mean * sc;
}

// ---------------- final BN apply: g_x0 -> d_out ----------------
__global__ void k_bn_apply_out(float* __restrict__ out_ext) {
    int i = blockIdx.x * blockDim.x + threadIdx.x;
    if (i >= NF4) return;
    int f4 = (i & 63) << 2;  // F/4 = 64 float4 groups per row
    float4 v  = reinterpret_cast<const float4*>(g_x0)[i];
    float4 sc = *reinterpret_cast<const float4*>(&g_scale[f4]);
    float4 sh = *reinterpret_cast<const float4*>(&g_shift[f4]);
    v.x = v.x * sc.x + sh.x;
    v.y = v.y * sc.y + sh.y;
    v.z = v.z * sc.z + sh.z;
    v.w = v.w * sc.w + sh.w;
    reinterpret_cast<float4*>(out_ext)[i] = v;
}

// ---------------- launch ----------------
extern "C" void kernel_launch(void* const* d_in, const int* in_sizes, int n_in,
                              void* d_out, int out_size) {
    const float* cell  = (const float*)d_in[0];
    const float* sub   = (const float*)d_in[1];
    const int*   ei    = (const int*)  d_in[2];
    const float* ew    = (const float*)d_in[3];
    const float* W1    = (const float*)d_in[4];
    const float* b1    = (const float*)d_in[5];
    const float* W2    = (const float*)d_in[6];
    const float* b2    = (const float*)d_in[7];
    const float* pw    = (const float*)d_in[8];
    const float* gamma = (const float*)d_in[9];
    const float* beta  = (const float*)d_in[10];
    float* out = (float*)d_out;

    const int T = 256;
    // graph normalization setup (recomputed each call — deterministic work)
    k_init<<<(N_NODES + T - 1) / T, T>>>();
    k_concat<<<(NF4 + T - 1) / T, T>>>((const float4*)cell, (const float4*)sub);
    k_degree<<<(E_TOT + T - 1) / T, T>>>(ei, ew);
    k_dinv<<<(N_NODES + T - 1) / T, T>>>();
    k_scan<<<1, 1024>>>();
    k_scatter<<<(E_TOT + T - 1) / T, T>>>(ei, ew);

    dim3 ggrid(GMB, FDIM / GBN);

    // ---- layer 1 ----
    k_spmm<true , false><<<N_NODES, T>>>();   // x0 -> x1
    k_spmm<false, false><<<N_NODES, T>>>();   // x1 -> x0
    k_spmm<true , false><<<N_NODES, T>>>();   // x0 -> x1
    k_gemm_fused<<<ggrid, T>>>(W1, b1, pw);   // x1 -> x0 (bias+prelu+stats)
    k_bn_finalize<<<1, FDIM>>>(gamma, beta);

    // ---- layer 2 (hop 1 folds layer-1 BN via linearity) ----
    k_spmm<true , true ><<<N_NODES, T>>>();   // x0 -> x1, applying scale/shift
    k_spmm<false, false><<<N_NODES, T>>>();
    k_spmm<true , false><<<N_NODES, T>>>();
    k_gemm_fused<<<ggrid, T>>>(W2, b2, pw);   // x1 -> x0
    k_bn_finalize<<<1, FDIM>>>(gamma, beta);
    k_bn_apply_out<<<(NF4 + T - 1) / T, T>>>(out);   // x0 -> d_out
}

// round 3
// speedup vs baseline: 1.4505x; 1.4505x over previous
#include <cuda_runtime.h>
#include <cuda_fp16.h>

// Problem constants (fixed shapes for this problem instance)
#define N_CELL   66
#define N_NODES  30000
#define FDIM     256
#define FD2      128               // half2 per row
#define E_TOT    960000            // directed edges (both directions)
#define NF       (N_NODES * FDIM)  // 7,680,000
#define NF4      (NF / 4)
#define CELL4    ((N_CELL * FDIM) / 4)
#define BN_EPS   1e-5f

// GEMM tiling
#define GBM 128
#define GBN 64
#define GBK 16
#define GMB 235                    // ceil(30000/128)

// ---------------- device scratch (static, no allocation) ----------------
__device__ __half2 g_hx0[N_NODES * FD2];   // fp16 feature ping
__device__ __half2 g_hx1[N_NODES * FD2];   // fp16 feature pong
__device__ float g_x1[NF];                 // fp32 GEMM input (hop-3 output)
__device__ float g_x0[NF];                 // fp32 GEMM2 output
__device__ float g_deg[N_NODES];
__device__ float g_dinv[N_NODES];
__device__ int   g_count[N_NODES];
__device__ int   g_colptr[N_NODES + 1];
__device__ int   g_cursor[N_NODES];
__device__ int2  g_epack[E_TOT];           // (src row, norm as bits)
__device__ float g_gp1[4 * GMB * GBN];     // per-block BN partial sums
__device__ float g_gp2[4 * GMB * GBN];     // per-block BN partial sumsq
__device__ float g_scale[FDIM];
__device__ float g_shift[FDIM];

// ---------------- packed f32x2 helpers ----------------
__device__ __forceinline__ unsigned long long pack2(float lo, float hi) {
    unsigned long long r;
    asm("mov.b64 %0, {%1, %2};" : "=l"(r) : "f"(lo), "f"(hi));
    return r;
}
__device__ __forceinline__ void unpack2(unsigned long long v, float& lo, float& hi) {
    asm("mov.b64 {%0, %1}, %2;" : "=f"(lo), "=f"(hi) : "l"(v));
}
__device__ __forceinline__ void ffma2(unsigned long long& d,
                                      unsigned long long a, unsigned long long b) {
    asm("fma.rn.f32x2 %0, %1, %2, %3;" : "=l"(d) : "l"(a), "l"(b), "l"(d));
}

// ---------------- setup kernels ----------------
__global__ void k_init() {
    int i = blockIdx.x * blockDim.x + threadIdx.x;
    if (i < N_NODES) { g_deg[i] = 1.0f; g_count[i] = 0; }  // self-loop weight = 1
}

// concat + fp16 quantize: x0 = half(concat(cell, sub))
__global__ void k_concat(const float4* __restrict__ cell, const float4* __restrict__ sub) {
    int i = blockIdx.x * blockDim.x + threadIdx.x;
    if (i >= NF4) return;
    float4 v = (i < CELL4) ? cell[i] : sub[i - CELL4];
    __half2 h0 = __floats2half2_rn(v.x, v.y);
    __half2 h1 = __floats2half2_rn(v.z, v.w);
    g_hx0[i * 2]     = h0;
    g_hx0[i * 2 + 1] = h1;
}

__global__ void k_degree(const int* __restrict__ ei, const float* __restrict__ ew) {
    int e = blockIdx.x * blockDim.x + threadIdx.x;
    if (e >= E_TOT) return;
    int c = ei[E_TOT + e];             // target (col)
    atomicAdd(&g_deg[c], ew[e]);
    atomicAdd(&g_count[c], 1);
}

__global__ void k_dinv() {
    int i = blockIdx.x * blockDim.x + threadIdx.x;
    if (i < N_NODES) g_dinv[i] = rsqrtf(g_deg[i]);   // deg >= 1 always
}

// single-block exclusive scan of g_count -> g_colptr / g_cursor
__global__ void k_scan() {
    __shared__ int sums[1024];
    int t = threadIdx.x;
    int base = t * 30;                 // 1024*30 = 30720 >= 30000
    int s = 0;
    for (int i = 0; i < 30; i++) {
        int idx = base + i;
        if (idx < N_NODES) s += g_count[idx];
    }
    sums[t] = s;
    __syncthreads();
    for (int off = 1; off < 1024; off <<= 1) {
        int v = (t >= off) ? sums[t - off] : 0;
        __syncthreads();
        sums[t] += v;
        __syncthreads();
    }
    int run = (t == 0) ? 0 : sums[t - 1];
    for (int i = 0; i < 30; i++) {
        int idx = base + i;
        if (idx < N_NODES) {
            g_colptr[idx] = run;
            g_cursor[idx] = run;
            run += g_count[idx];
        }
    }
    if (t == 1023) g_colptr[N_NODES] = E_TOT;
}

__global__ void k_scatter(const int* __restrict__ ei, const float* __restrict__ ew) {
    int e = blockIdx.x * blockDim.x + threadIdx.x;
    if (e >= E_TOT) return;
    int r = ei[e];
    int c = ei[E_TOT + e];
    int pos = atomicAdd(&g_cursor[c], 1);
    float nrm = g_dinv[r] * ew[e] * g_dinv[c];
    g_epack[pos] = make_int2(r, __float_as_int(nrm));
}

// ---------------- SpMM (fp16 gather): one block of 128 thr per dest node ----
// SRC0: src = hx0 else hx1 (dst = the other)
// FOLD: out = scale[f]*acc + shift[f]*sum_w   (BN applied via linearity)
// OUTF32: write fp32 to g_x1 (GEMM input) instead of half dst
template <bool SRC0, bool FOLD, bool OUTF32>
__global__ __launch_bounds__(128) void k_spmm() {
    const __half2* __restrict__ xin = SRC0 ? g_hx0 : g_hx1;
    __half2*       __restrict__ xhout = SRC0 ? g_hx1 : g_hx0;
    int i  = blockIdx.x;
    int f2 = threadIdx.x;                 // 0..127 -> features 2f2, 2f2+1
    int beg = g_colptr[i];
    int end = g_colptr[i + 1];
    float di = g_dinv[i];
    float selfw = di * di;
    float2 xv = __half22float2(xin[i * FD2 + f2]);
    float acc0 = selfw * xv.x;
    float acc1 = selfw * xv.y;
    float sw   = selfw;
#pragma unroll 4
    for (int e = beg; e < end; e++) {
        int2  p = g_epack[e];
        float w = __int_as_float(p.y);
        float2 v = __half22float2(xin[p.x * FD2 + f2]);
        acc0 += w * v.x;
        acc1 += w * v.y;
        sw   += w;
    }
    if (FOLD) {
        float2 sc = *reinterpret_cast<const float2*>(&g_scale[f2 * 2]);
        float2 sh = *reinterpret_cast<const float2*>(&g_shift[f2 * 2]);
        acc0 = sc.x * acc0 + sh.x * sw;
        acc1 = sc.y * acc1 + sh.y * sw;
    }
    if (OUTF32) {
        *reinterpret_cast<float2*>(&g_x1[(size_t)i * FDIM + f2 * 2]) =
            make_float2(acc0, acc1);
    } else {
        xhout[i * FD2 + f2] = __floats2half2_rn(acc0, acc1);
    }
}

// ---------------- fused GEMM: C = prelu(A @ W^T + b), + BN partial stats ----
// A = g_x1 [N,256].  OUT_HALF: store fp16 to g_hx0 (layer-1) else fp32 g_x0.
template <bool OUT_HALF>
__global__ __launch_bounds__(256) void k_gemm_fused(const float* __restrict__ W,
                                                    const float* __restrict__ bias,
                                                    const float* __restrict__ pw) {
    __shared__ __align__(16) float As[GBK][GBM];   // k-major
    __shared__ __align__(16) float Bs[GBK][GBN];   // k-major
    __shared__ float Red[16][GBN];

    const float* __restrict__ A = g_x1;

    int bm = blockIdx.x * GBM;
    int bn = blockIdx.y * GBN;
    int t  = threadIdx.x;
    int tn  = t & 15;          // n-group (4 cols)
    int tmg = t >> 4;          // m-group (8 rows), 0..15

    int lm  = t & 127;
    int lk8 = (t >> 7) * 8;
    int gm_ld = bm + lm;
    const float* Aptr = A + (size_t)gm_ld * FDIM + lk8;
    int ln  = t & 63;
    int lk4 = (t >> 6) * 4;
    const float* Wptr = W + (size_t)(bn + ln) * FDIM + lk4;

    unsigned long long acc[4][4];
#pragma unroll
    for (int i = 0; i < 4; i++)
#pragma unroll
        for (int j = 0; j < 4; j++) acc[i][j] = 0ull;

    for (int k0 = 0; k0 < FDIM; k0 += GBK) {
        float4 a0 = make_float4(0.f, 0.f, 0.f, 0.f);
        float4 a1 = make_float4(0.f, 0.f, 0.f, 0.f);
        if (gm_ld < N_NODES) {
            a0 = *reinterpret_cast<const float4*>(Aptr + k0);
            a1 = *reinterpret_cast<const float4*>(Aptr + k0 + 4);
        }
        float4 bv = *reinterpret_cast<const float4*>(Wptr + k0);
        As[lk8 + 0][lm] = a0.x; As[lk8 + 1][lm] = a0.y;
        As[lk8 + 2][lm] = a0.z; As[lk8 + 3][lm] = a0.w;
        As[lk8 + 4][lm] = a1.x; As[lk8 + 5][lm] = a1.y;
        As[lk8 + 6][lm] = a1.z; As[lk8 + 7][lm] = a1.w;
        Bs[lk4 + 0][ln] = bv.x; Bs[lk4 + 1][ln] = bv.y;
        Bs[lk4 + 2][ln] = bv.z; Bs[lk4 + 3][ln] = bv.w;
        __syncthreads();
#pragma unroll
        for (int kk = 0; kk < GBK; kk++) {
            ulonglong2 a01 = *reinterpret_cast<const ulonglong2*>(&As[kk][tmg * 8]);
            ulonglong2 a23 = *reinterpret_cast<const ulonglong2*>(&As[kk][tmg * 8 + 4]);
            float4 b = *reinterpret_cast<const float4*>(&Bs[kk][tn * 4]);
            unsigned long long b0 = pack2(b.x, b.x);
            unsigned long long b1 = pack2(b.y, b.y);
            unsigned long long b2 = pack2(b.z, b.z);
            unsigned long long b3 = pack2(b.w, b.w);
            ffma2(acc[0][0], a01.x, b0); ffma2(acc[0][1], a01.x, b1);
            ffma2(acc[0][2], a01.x, b2); ffma2(acc[0][3], a01.x, b3);
            ffma2(acc[1][0], a01.y, b0); ffma2(acc[1][1], a01.y, b1);
            ffma2(acc[1][2], a01.y, b2); ffma2(acc[1][3], a01.y, b3);
            ffma2(acc[2][0], a23.x, b0); ffma2(acc[2][1], a23.x, b1);
            ffma2(acc[2][2], a23.x, b2); ffma2(acc[2][3], a23.x, b3);
            ffma2(acc[3][0], a23.y, b0); ffma2(acc[3][1], a23.y, b1);
            ffma2(acc[3][2], a23.y, b2); ffma2(acc[3][3], a23.y, b3);
        }
        __syncthreads();
    }

    // -------- epilogue: bias + PReLU + store + per-column partial stats ------
    int n0 = bn + tn * 4;
    float4 bb  = *reinterpret_cast<const float4*>(&bias[n0]);
    float4 pwv = *reinterpret_cast<const float4*>(&pw[n0]);
    float cs[4]  = {0.f, 0.f, 0.f, 0.f};
    float cs2[4] = {0.f, 0.f, 0.f, 0.f};
#pragma unroll
    for (int mp = 0; mp < 4; mp++) {
        float v0[4], v1[4];
        unpack2(acc[mp][0], v0[0], v1[0]);
        unpack2(acc[mp][1], v0[1], v1[1]);
        unpack2(acc[mp][2], v0[2], v1[2]);
        unpack2(acc[mp][3], v0[3], v1[3]);
        int m0 = bm + tmg * 8 + mp * 2;
#pragma unroll
        for (int h = 0; h < 2; h++) {
            float* v = h ? v1 : v0;
            int m = m0 + h;
            v[0] += bb.x; v[1] += bb.y; v[2] += bb.z; v[3] += bb.w;
            v[0] = (v[0] >= 0.f) ? v[0] : pwv.x * v[0];
            v[1] = (v[1] >= 0.f) ? v[1] : pwv.y * v[1];
            v[2] = (v[2] >= 0.f) ? v[2] : pwv.z * v[2];
            v[3] = (v[3] >= 0.f) ? v[3] : pwv.w * v[3];
            if (m < N_NODES) {
                if (OUT_HALF) {
                    __half2 h2a = __floats2half2_rn(v[0], v[1]);
                    __half2 h2b = __floats2half2_rn(v[2], v[3]);
                    __half2* dst = &g_hx0[m * FD2 + n0 / 2];
                    dst[0] = h2a;
                    dst[1] = h2b;
                } else {
                    *reinterpret_cast<float4*>(&g_x0[(size_t)m * FDIM + n0]) =
                        make_float4(v[0], v[1], v[2], v[3]);
                }
#pragma unroll
                for (int i = 0; i < 4; i++) { cs[i] += v[i]; cs2[i] += v[i] * v[i]; }
            }
        }
    }

    // deterministic in-block column reduction (no atomics)
    int pbase = (blockIdx.y * GMB + blockIdx.x) * GBN;
#pragma unroll
    for (int i = 0; i < 4; i++) Red[tmg][tn * 4 + i] = cs[i];
    __syncthreads();
    if (t < GBN) {
        float s = 0.f;
#pragma unroll
        for (int r = 0; r < 16; r++) s += Red[r][t];
        g_gp1[pbase + t] = s;
    }
    __syncthreads();
#pragma unroll
    for (int i = 0; i < 4; i++) Red[tmg][tn * 4 + i] = cs2[i];
    __syncthreads();
    if (t < GBN) {
        float s = 0.f;
#pragma unroll
        for (int r = 0; r < 16; r++) s += Red[r][t];
        g_gp2[pbase + t] = s;
    }
}

// ---------------- BN finalize: reduce per-block partials -> scale/shift -----
__global__ void k_bn_finalize(const float* __restrict__ gamma,
                              const float* __restrict__ beta) {
    int f  = threadIdx.x;         // 256 threads, 1 block — deterministic order
    int by = f >> 6;
    int c  = f & 63;
    float s = 0.f, s2 = 0.f;
    for (int bx = 0; bx < GMB; bx++) {
        int idx = (by * GMB + bx) * GBN + c;
        s  += g_gp1[idx];
        s2 += g_gp2[idx];
    }
    float inv_n = 1.0f / (float)N_NODES;
    float mean = s * inv_n;
    float var  = s2 * inv_n - mean * mean;
    float sc   = gamma[f] * rsqrtf(var + BN_EPS);
    g_scale[f] = sc;
    g_shift[f] = beta[f] - mean * sc;
}

// ---------------- final BN apply: g_x0 -> d_out ----------------
__global__ void k_bn_apply_out(float* __restrict__ out_ext) {
    int i = blockIdx.x * blockDim.x + threadIdx.x;
    if (i >= NF4) return;
    int f4 = (i & 63) << 2;
    float4 v  = reinterpret_cast<const float4*>(g_x0)[i];
    float4 sc = *reinterpret_cast<const float4*>(&g_scale[f4]);
    float4 sh = *reinterpret_cast<const float4*>(&g_shift[f4]);
    v.x = v.x * sc.x + sh.x;
    v.y = v.y * sc.y + sh.y;
    v.z = v.z * sc.z + sh.z;
    v.w = v.w * sc.w + sh.w;
    reinterpret_cast<float4*>(out_ext)[i] = v;
}

// ---------------- launch ----------------
extern "C" void kernel_launch(void* const* d_in, const int* in_sizes, int n_in,
                              void* d_out, int out_size) {
    const float* cell  = (const float*)d_in[0];
    const float* sub   = (const float*)d_in[1];
    const int*   ei    = (const int*)  d_in[2];
    const float* ew    = (const float*)d_in[3];
    const float* W1    = (const float*)d_in[4];
    const float* b1    = (const float*)d_in[5];
    const float* W2    = (const float*)d_in[6];
    const float* b2    = (const float*)d_in[7];
    const float* pw    = (const float*)d_in[8];
    const float* gamma = (const float*)d_in[9];
    const float* beta  = (const float*)d_in[10];
    float* out = (float*)d_out;

    const int T = 256;
    // graph normalization setup (recomputed each call — deterministic work)
    k_init<<<(N_NODES + T - 1) / T, T>>>();
    k_concat<<<(NF4 + T - 1) / T, T>>>((const float4*)cell, (const float4*)sub);
    k_degree<<<(E_TOT + T - 1) / T, T>>>(ei, ew);
    k_dinv<<<(N_NODES + T - 1) / T, T>>>();
    k_scan<<<1, 1024>>>();
    k_scatter<<<(E_TOT + T - 1) / T, T>>>(ei, ew);

    dim3 ggrid(GMB, FDIM / GBN);

    // ---- layer 1 (fp16 hops; hop3 emits fp32 GEMM input) ----
    k_spmm<true , false, false><<<N_NODES, 128>>>();  // hx0 -> hx1
    k_spmm<false, false, false><<<N_NODES, 128>>>();  // hx1 -> hx0
    k_spmm<true , false, true ><<<N_NODES, 128>>>();  // hx0 -> g_x1 (fp32)
    k_gemm_fused<true ><<<ggrid, T>>>(W1, b1, pw);    // g_x1 -> hx0 (fp16) + stats
    k_bn_finalize<<<1, FDIM>>>(gamma, beta);

    // ---- layer 2 (hop 1 folds layer-1 BN via linearity) ----
    k_spmm<true , true , false><<<N_NODES, 128>>>();  // hx0 -> hx1 (BN folded)
    k_spmm<false, false, false><<<N_NODES, 128>>>();  // hx1 -> hx0
    k_spmm<true , false, true ><<<N_NODES, 128>>>();  // hx0 -> g_x1 (fp32)
    k_gemm_fused<false><<<ggrid, T>>>(W2, b2, pw);    // g_x1 -> g_x0 (fp32) + stats
    k_bn_finalize<<<1, FDIM>>>(gamma, beta);
    k_bn_apply_out<<<(NF4 + T - 1) / T, T>>>(out);    // g_x0 -> d_out
}

// round 5
// speedup vs baseline: 1.9266x; 1.3283x over previous
#include <cuda_runtime.h>
#include <cuda_fp16.h>
#include <mma.h>

using namespace nvcuda;

// Problem constants (fixed shapes for this problem instance)
#define N_CELL   66
#define N_NODES  30000
#define FDIM     256
#define FD2      128               // half2 per row
#define E_TOT    960000            // directed edges (both directions)
#define NF       (N_NODES * FDIM)  // 7,680,000
#define NF4      (NF / 4)
#define CELL4    ((N_CELL * FDIM) / 4)
#define BN_EPS   1e-5f

// GEMM tiling
#define GBM 128
#define GBN 64
#define GBK 32
#define GMB 235                    // ceil(30000/128)
#define LDA 40                     // smem half stride (128 rows x 32 k, +8 pad)
#define LDC 72                     // smem float stride (128 rows x 64 n, +8 pad)

// ---------------- device scratch (static, no allocation) ----------------
__device__ __half2 g_hx0[N_NODES * FD2];   // fp16 feature ping
__device__ __half2 g_hx1[N_NODES * FD2];   // fp16 feature pong
__device__ float  g_x0[NF];                // fp32 GEMM2 output
__device__ __half g_hw1[FDIM * FDIM];      // fp16 W1
__device__ __half g_hw2[FDIM * FDIM];      // fp16 W2
__device__ float g_deg[N_NODES];
__device__ float g_dinv[N_NODES];
__device__ int   g_count[N_NODES];
__device__ int   g_colptr[N_NODES + 1];
__device__ int   g_cursor[N_NODES];
__device__ int2  g_epack[E_TOT];           // (src row, norm as bits)
__device__ float g_gp1[4 * GMB * GBN];     // per-block BN partial sums
__device__ float g_gp2[4 * GMB * GBN];     // per-block BN partial sumsq
__device__ float g_scale[FDIM];
__device__ float g_shift[FDIM];

// ---------------- setup kernels ----------------
__global__ void k_init() {
    int i = blockIdx.x * blockDim.x + threadIdx.x;
    if (i < N_NODES) { g_deg[i] = 1.0f; g_count[i] = 0; }  // self-loop weight = 1
}

// concat + fp16 quantize: hx0 = half(concat(cell, sub))
__global__ void k_concat(const float4* __restrict__ cell, const float4* __restrict__ sub) {
    int i = blockIdx.x * blockDim.x + threadIdx.x;
    if (i >= NF4) return;
    float4 v = (i < CELL4) ? cell[i] : sub[i - CELL4];
    g_hx0[i * 2]     = __floats2half2_rn(v.x, v.y);
    g_hx0[i * 2 + 1] = __floats2half2_rn(v.z, v.w);
}

// convert W1, W2 to fp16
__global__ void k_wcvt(const float* __restrict__ W1, const float* __restrict__ W2) {
    int i = blockIdx.x * blockDim.x + threadIdx.x;
    if (i < FDIM * FDIM) {
        g_hw1[i] = __float2half_rn(W1[i]);
        g_hw2[i] = __float2half_rn(W2[i]);
    }
}

__global__ void k_degree(const int* __restrict__ ei, const float* __restrict__ ew) {
    int e = blockIdx.x * blockDim.x + threadIdx.x;
    if (e >= E_TOT) return;
    int c = ei[E_TOT + e];             // target (col)
    atomicAdd(&g_deg[c], ew[e]);
    atomicAdd(&g_count[c], 1);
}

__global__ void k_dinv() {
    int i = blockIdx.x * blockDim.x + threadIdx.x;
    if (i < N_NODES) g_dinv[i] = rsqrtf(g_deg[i]);   // deg >= 1 always
}

// single-block exclusive scan of g_count -> g_colptr / g_cursor
__global__ void k_scan() {
    __shared__ int sums[1024];
    int t = threadIdx.x;
    int base = t * 30;                 // 1024*30 = 30720 >= 30000
    int s = 0;
    for (int i = 0; i < 30; i++) {
        int idx = base + i;
        if (idx < N_NODES) s += g_count[idx];
    }
    sums[t] = s;
    __syncthreads();
    for (int off = 1; off < 1024; off <<= 1) {
        int v = (t >= off) ? sums[t - off] : 0;
        __syncthreads();
        sums[t] += v;
        __syncthreads();
    }
    int run = (t == 0) ? 0 : sums[t - 1];
    for (int i = 0; i < 30; i++) {
        int idx = base + i;
        if (idx < N_NODES) {
            g_colptr[idx] = run;
            g_cursor[idx] = run;
            run += g_count[idx];
        }
    }
    if (t == 1023) g_colptr[N_NODES] = E_TOT;
}

__global__ void k_scatter(const int* __restrict__ ei, const float* __restrict__ ew) {
    int e = blockIdx.x * blockDim.x + threadIdx.x;
    if (e >= E_TOT) return;
    int r = ei[e];
    int c = ei[E_TOT + e];
    int pos = atomicAdd(&g_cursor[c], 1);
    float nrm = g_dinv[r] * ew[e] * g_dinv[c];
    g_epack[pos] = make_int2(r, __float_as_int(nrm));
}

// ---------------- SpMM (fp16 gather): one block of 128 thr per dest node ----
// SRC0: src = hx0, dst = hx1 (else swapped)
// FOLD: out = scale[f]*acc + shift[f]*sum_w   (BN applied via linearity)
template <bool SRC0, bool FOLD>
__global__ __launch_bounds__(128) void k_spmm() {
    const __half2* __restrict__ xin   = SRC0 ? g_hx0 : g_hx1;
    __half2*       __restrict__ xhout = SRC0 ? g_hx1 : g_hx0;
    int i  = blockIdx.x;
    int f2 = threadIdx.x;                 // 0..127 -> features 2f2, 2f2+1
    int beg = g_colptr[i];
    int end = g_colptr[i + 1];
    float di = g_dinv[i];
    float selfw = di * di;
    float2 xv = __half22float2(xin[i * FD2 + f2]);
    float acc0 = selfw * xv.x;
    float acc1 = selfw * xv.y;
    float sw   = selfw;
#pragma unroll 4
    for (int e = beg; e < end; e++) {
        int2  p = g_epack[e];
        float w = __int_as_float(p.y);
        float2 v = __half22float2(xin[p.x * FD2 + f2]);
        acc0 += w * v.x;
        acc1 += w * v.y;
        sw   += w;
    }
    if (FOLD) {
        float2 sc = *reinterpret_cast<const float2*>(&g_scale[f2 * 2]);
        float2 sh = *reinterpret_cast<const float2*>(&g_shift[f2 * 2]);
        acc0 = sc.x * acc0 + sh.x * sw;
        acc1 = sc.y * acc1 + sh.y * sw;
    }
    xhout[i * FD2 + f2] = __floats2half2_rn(acc0, acc1);
}

// ------- fused tensor-core GEMM: C = prelu(A @ W^T + b), + BN stats --------
// A = g_hx1 [N,256] fp16 row-major.  W fp16 [256,256] row-major (= B col-major).
// USE_W1 selects the __device__ weight array (no host-side symbol reference!).
// OUT_HALF: store fp16 to g_hx0 (layer-1) else fp32 g_x0 (layer-2).
template <bool USE_W1, bool OUT_HALF>
__global__ __launch_bounds__(256) void k_gemm_tc(const float* __restrict__ bias,
                                                 const float* __restrict__ pw) {
    // smem: mainloop A/B tiles overlap epilogue C staging
    __shared__ __align__(16) unsigned char raw[GBM * LDC * 4 + 16 * GBN * 4];
    __half* As = reinterpret_cast<__half*>(raw);                 // [128][LDA]
    __half* Bs = reinterpret_cast<__half*>(raw + GBM * LDA * 2); // [64][LDA]
    float*  Cs = reinterpret_cast<float*>(raw);                  // [128][LDC]
    float(*Red)[GBN] = reinterpret_cast<float(*)[GBN]>(raw + GBM * LDC * 4);

    const __half* __restrict__ A  = reinterpret_cast<const __half*>(g_hx1);
    const __half* __restrict__ hW = USE_W1 ? g_hw1 : g_hw2;

    int bm = blockIdx.x * GBM;
    int bn = blockIdx.y * GBN;
    int t  = threadIdx.x;
    int wid = t >> 5;
    int wm  = wid >> 1;          // 0..3 : warp row (32 rows each)
    int wn  = wid & 1;           // 0..1 : warp col (32 cols each)

    // A loader: 128 rows x 32 halves; thread: row = t>>1, 16 halves at (t&1)*16
    int arow = t >> 1;
    int aseg = (t & 1) * 16;
    int gm_ld = bm + arow;
    // B loader: 64 rows(n) x 32 halves(k); thread: n = t>>2, 8 halves at (t&3)*8
    int brow = t >> 2;
    int bseg = (t & 3) * 8;

    wmma::fragment<wmma::accumulator, 16, 16, 16, float> c[2][2];
#pragma unroll
    for (int i = 0; i < 2; i++)
#pragma unroll
        for (int j = 0; j < 2; j++) wmma::fill_fragment(c[i][j], 0.0f);

    for (int k0 = 0; k0 < FDIM; k0 += GBK) {
        // load A tile (zero-fill OOB rows)
        uint4 a0 = make_uint4(0u, 0u, 0u, 0u), a1 = a0;
        if (gm_ld < N_NODES) {
            const uint4* src = reinterpret_cast<const uint4*>(
                A + (size_t)gm_ld * FDIM + k0 + aseg);
            a0 = src[0]; a1 = src[1];
        }
        uint4* dstA = reinterpret_cast<uint4*>(&As[arow * LDA + aseg]);
        dstA[0] = a0; dstA[1] = a1;
        // load B tile (W rows bn..bn+63)
        const uint4* srcB = reinterpret_cast<const uint4*>(
            hW + (size_t)(bn + brow) * FDIM + k0 + bseg);
        *reinterpret_cast<uint4*>(&Bs[brow * LDA + bseg]) = srcB[0];
        __syncthreads();
#pragma unroll
        for (int kk = 0; kk < GBK; kk += 16) {
            wmma::fragment<wmma::matrix_a, 16, 16, 16, __half, wmma::row_major> af[2];
            wmma::fragment<wmma::matrix_b, 16, 16, 16, __half, wmma::col_major> bf[2];
#pragma unroll
            for (int i = 0; i < 2; i++)
                wmma::load_matrix_sync(af[i], &As[(wm * 32 + i * 16) * LDA + kk], LDA);
#pragma unroll
            for (int j = 0; j < 2; j++)
                wmma::load_matrix_sync(bf[j], &Bs[(wn * 32 + j * 16) * LDA + kk], LDA);
#pragma unroll
            for (int i = 0; i < 2; i++)
#pragma unroll
                for (int j = 0; j < 2; j++)
                    wmma::mma_sync(c[i][j], af[i], bf[j], c[i][j]);
        }
        __syncthreads();
    }

    // stage C to smem (overlaps As/Bs — separated by the final __syncthreads)
#pragma unroll
    for (int i = 0; i < 2; i++)
#pragma unroll
        for (int j = 0; j < 2; j++)
            wmma::store_matrix_sync(&Cs[(wm * 32 + i * 16) * LDC + wn * 32 + j * 16],
                                    c[i][j], LDC, wmma::mem_row_major);
    __syncthreads();

    // -------- epilogue: bias + PReLU + store + per-column partial stats ------
    int tn  = t & 15;          // 4-col group
    int tmg = t >> 4;          // 8-row group
    int n0 = bn + tn * 4;
    float4 bb  = *reinterpret_cast<const float4*>(&bias[n0]);
    float4 pwv = *reinterpret_cast<const float4*>(&pw[n0]);
    float cs[4]  = {0.f, 0.f, 0.f, 0.f};
    float cs2[4] = {0.f, 0.f, 0.f, 0.f};
#pragma unroll
    for (int r = 0; r < 8; r++) {
        int lr = tmg * 8 + r;
        int m  = bm + lr;
        float4 v = *reinterpret_cast<const float4*>(&Cs[lr * LDC + tn * 4]);
        v.x += bb.x; v.y += bb.y; v.z += bb.z; v.w += bb.w;
        v.x = (v.x >= 0.f) ? v.x : pwv.x * v.x;
        v.y = (v.y >= 0.f) ? v.y : pwv.y * v.y;
        v.z = (v.z >= 0.f) ? v.z : pwv.z * v.z;
        v.w = (v.w >= 0.f) ? v.w : pwv.w * v.w;
        if (m < N_NODES) {
            if (OUT_HALF) {
                __half2* dst = &g_hx0[m * FD2 + n0 / 2];
                dst[0] = __floats2half2_rn(v.x, v.y);
                dst[1] = __floats2half2_rn(v.z, v.w);
            } else {
                *reinterpret_cast<float4*>(&g_x0[(size_t)m * FDIM + n0]) = v;
            }
            cs[0] += v.x; cs[1] += v.y; cs[2] += v.z; cs[3] += v.w;
            cs2[0] += v.x * v.x; cs2[1] += v.y * v.y;
            cs2[2] += v.z * v.z; cs2[3] += v.w * v.w;
        }
    }

    // deterministic in-block column reduction (no atomics)
    int pbase = (blockIdx.y * GMB + blockIdx.x) * GBN;
#pragma unroll
    for (int i = 0; i < 4; i++) Red[tmg][tn * 4 + i] = cs[i];
    __syncthreads();
    if (t < GBN) {
        float s = 0.f;
#pragma unroll
        for (int r = 0; r < 16; r++) s += Red[r][t];
        g_gp1[pbase + t] = s;
    }
    __syncthreads();
#pragma unroll
    for (int i = 0; i < 4; i++) Red[tmg][tn * 4 + i] = cs2[i];
    __syncthreads();
    if (t < GBN) {
        float s = 0.f;
#pragma unroll
        for (int r = 0; r < 16; r++) s += Red[r][t];
        g_gp2[pbase + t] = s;
    }
}

// ---------------- BN finalize: reduce per-block partials -> scale/shift -----
__global__ void k_bn_finalize(const float* __restrict__ gamma,
                              const float* __restrict__ beta) {
    int f  = threadIdx.x;         // 256 threads, 1 block — deterministic order
    int by = f >> 6;
    int c  = f & 63;
    float s = 0.f, s2 = 0.f;
    for (int bx = 0; bx < GMB; bx++) {
        int idx = (by * GMB + bx) * GBN + c;
        s  += g_gp1[idx];
        s2 += g_gp2[idx];
    }
    float inv_n = 1.0f / (float)N_NODES;
    float mean = s * inv_n;
    float var  = s2 * inv_n - mean * mean;
    float sc   = gamma[f] * rsqrtf(var + BN_EPS);
    g_scale[f] = sc;
    g_shift[f] = beta[f] - mean * sc;
}

// ---------------- final BN apply: g_x0 -> d_out ----------------
__global__ void k_bn_apply_out(float* __restrict__ out_ext) {
    int i = blockIdx.x * blockDim.x + threadIdx.x;
    if (i >= NF4) return;
    int f4 = (i & 63) << 2;
    float4 v  = reinterpret_cast<const float4*>(g_x0)[i];
    float4 sc = *reinterpret_cast<const float4*>(&g_scale[f4]);
    float4 sh = *reinterpret_cast<const float4*>(&g_shift[f4]);
    v.x = v.x * sc.x + sh.x;
    v.y = v.y * sc.y + sh.y;
    v.z = v.z * sc.z + sh.z;
    v.w = v.w * sc.w + sh.w;
    reinterpret_cast<float4*>(out_ext)[i] = v;
}

// ---------------- launch ----------------
extern "C" void kernel_launch(void* const* d_in, const int* in_sizes, int n_in,
                              void* d_out, int out_size) {
    const float* cell  = (const float*)d_in[0];
    const float* sub   = (const float*)d_in[1];
    const int*   ei    = (const int*)  d_in[2];
    const float* ew    = (const float*)d_in[3];
    const float* W1    = (const float*)d_in[4];
    const float* b1    = (const float*)d_in[5];
    const float* W2    = (const float*)d_in[6];
    const float* b2    = (const float*)d_in[7];
    const float* pw    = (const float*)d_in[8];
    const float* gamma = (const float*)d_in[9];
    const float* beta  = (const float*)d_in[10];
    float* out = (float*)d_out;

    const int T = 256;
    // graph normalization setup (recomputed each call — deterministic work)
    k_init<<<(N_NODES + T - 1) / T, T>>>();
    k_concat<<<(NF4 + T - 1) / T, T>>>((const float4*)cell, (const float4*)sub);
    k_wcvt<<<(FDIM * FDIM + T - 1) / T, T>>>(W1, W2);
    k_degree<<<(E_TOT + T - 1) / T, T>>>(ei, ew);
    k_dinv<<<(N_NODES + T - 1) / T, T>>>();
    k_scan<<<1, 1024>>>();
    k_scatter<<<(E_TOT + T - 1) / T, T>>>(ei, ew);

    dim3 ggrid(GMB, FDIM / GBN);   // (235, 4)

    // ---- layer 1 (fp16 hops) ----
    k_spmm<true , false><<<N_NODES, 128>>>();   // hx0 -> hx1
    k_spmm<false, false><<<N_NODES, 128>>>();   // hx1 -> hx0
    k_spmm<true , false><<<N_NODES, 128>>>();   // hx0 -> hx1
    k_gemm_tc<true , true ><<<ggrid, T>>>(b1, pw);  // hx1 -> hx0 (fp16) + stats
    k_bn_finalize<<<1, FDIM>>>(gamma, beta);

    // ---- layer 2 (hop 1 folds layer-1 BN via linearity) ----
    k_spmm<true , true ><<<N_NODES, 128>>>();   // hx0 -> hx1 (BN folded)
    k_spmm<false, false><<<N_NODES, 128>>>();   // hx1 -> hx0
    k_spmm<true , false><<<N_NODES, 128>>>();   // hx0 -> hx1
    k_gemm_tc<false, false><<<ggrid, T>>>(b2, pw);  // hx1 -> g_x0 (fp32) + stats
    k_bn_finalize<<<1, FDIM>>>(gamma, beta);
    k_bn_apply_out<<<(NF4 + T - 1) / T, T>>>(out);  // g_x0 -> d_out
}

// round 7
// speedup vs baseline: 2.2671x; 1.1767x over previous
#include <cuda_runtime.h>
#include <cuda_fp16.h>
#include <mma.h>

using namespace nvcuda;

// Problem constants (fixed shapes for this problem instance)
#define N_CELL   66
#define N_NODES  30000
#define FDIM     256
#define FD2      128               // half2 per row
#define E_TOT    960000            // directed edges (both directions)
#define NF       (N_NODES * FDIM)  // 7,680,000
#define NF4      (NF / 4)
#define CELL4    ((N_CELL * FDIM) / 4)
#define BN_EPS   1e-5f

// GEMM tiling
#define GBM 128
#define GBN 64
#define GBK 32
#define GMB 235                    // ceil(30000/128)
#define LDA 40                     // smem half stride (128 rows x 32 k, +8 pad)
#define LDC 72                     // smem float stride (128 rows x 64 n, +8 pad)

// ---------------- device scratch (static, no allocation) ----------------
__device__ __half2 g_hx0[N_NODES * FD2];   // fp16 feature ping
__device__ __half2 g_hx1[N_NODES * FD2];   // fp16 feature pong
__device__ float  g_x0[NF];                // fp32 GEMM2 output
__device__ __half g_hw1[FDIM * FDIM];      // fp16 W1
__device__ __half g_hw2[FDIM * FDIM];      // fp16 W2
__device__ float g_deg[N_NODES];
__device__ float g_dinv[N_NODES];
__device__ int   g_count[N_NODES];
__device__ int   g_colptr[N_NODES + 1];
__device__ int   g_cursor[N_NODES];
__device__ int2  g_epack[E_TOT];           // (src row, norm as bits)
__device__ float g_gp1[4 * GMB * GBN];     // per-block BN partial sums
__device__ float g_gp2[4 * GMB * GBN];     // per-block BN partial sumsq
__device__ float g_scale[FDIM];
__device__ float g_shift[FDIM];

// ---------------- setup kernels ----------------
__global__ void k_init() {
    int i = blockIdx.x * blockDim.x + threadIdx.x;
    if (i < N_NODES) { g_deg[i] = 1.0f; g_count[i] = 0; }  // self-loop weight = 1
}

// concat + fp16 quantize: hx0 = half(concat(cell, sub))
__global__ void k_concat(const float4* __restrict__ cell, const float4* __restrict__ sub) {
    int i = blockIdx.x * blockDim.x + threadIdx.x;
    if (i >= NF4) return;
    float4 v = (i < CELL4) ? cell[i] : sub[i - CELL4];
    g_hx0[i * 2]     = __floats2half2_rn(v.x, v.y);
    g_hx0[i * 2 + 1] = __floats2half2_rn(v.z, v.w);
}

// convert W1, W2 to fp16
__global__ void k_wcvt(const float* __restrict__ W1, const float* __restrict__ W2) {
    int i = blockIdx.x * blockDim.x + threadIdx.x;
    if (i < FDIM * FDIM) {
        g_hw1[i] = __float2half_rn(W1[i]);
        g_hw2[i] = __float2half_rn(W2[i]);
    }
}

__global__ void k_degree(const int* __restrict__ ei, const float* __restrict__ ew) {
    int e = blockIdx.x * blockDim.x + threadIdx.x;
    if (e >= E_TOT) return;
    int c = ei[E_TOT + e];             // target (col)
    atomicAdd(&g_deg[c], ew[e]);
    atomicAdd(&g_count[c], 1);
}

// single-block: dinv + exclusive scan of g_count -> g_colptr / g_cursor
__global__ void k_scan() {
    __shared__ int sums[1024];
    int t = threadIdx.x;
    int base = t * 30;                 // 1024*30 = 30720 >= 30000
    int s = 0;
    for (int i = 0; i < 30; i++) {
        int idx = base + i;
        if (idx < N_NODES) {
            g_dinv[idx] = rsqrtf(g_deg[idx]);   // deg >= 1 always
            s += g_count[idx];
        }
    }
    sums[t] = s;
    __syncthreads();
    for (int off = 1; off < 1024; off <<= 1) {
        int v = (t >= off) ? sums[t - off] : 0;
        __syncthreads();
        sums[t] += v;
        __syncthreads();
    }
    int run = (t == 0) ? 0 : sums[t - 1];
    for (int i = 0; i < 30; i++) {
        int idx = base + i;
        if (idx < N_NODES) {
            g_colptr[idx] = run;
            g_cursor[idx] = run;
            run += g_count[idx];
        }
    }
    if (t == 1023) g_colptr[N_NODES] = E_TOT;
}

__global__ void k_scatter(const int* __restrict__ ei, const float* __restrict__ ew) {
    int e = blockIdx.x * blockDim.x + threadIdx.x;
    if (e >= E_TOT) return;
    int r = ei[e];
    int c = ei[E_TOT + e];
    int pos = atomicAdd(&g_cursor[c], 1);
    float nrm = g_dinv[r] * ew[e] * g_dinv[c];
    g_epack[pos] = make_int2(r, __float_as_int(nrm));
}

// ---------------- SpMM (warp-per-edge gather): one block per dest node -----
// 4 warps split the edge list (e % 4 == wid); each lane loads 16B (8 feats)
// of the source row via LDG.128. Partials combined in smem, fixed warp order.
// SRC0: src = hx0, dst = hx1 (else swapped)
// FOLD: out = scale[f]*acc + shift[f]*sum_w   (BN applied via linearity)
template <bool SRC0, bool FOLD>
__global__ __launch_bounds__(128) void k_spmm() {
    const __half2* __restrict__ xin  = SRC0 ? g_hx0 : g_hx1;
    __half2*       __restrict__ xout = SRC0 ? g_hx1 : g_hx0;
    __shared__ float sred[4][FDIM];
    __shared__ float swred[4];

    int i   = blockIdx.x;
    int t   = threadIdx.x;
    int wid = t >> 5;
    int lid = t & 31;
    int beg = g_colptr[i];
    int end = g_colptr[i + 1];

    float acc[8] = {0.f, 0.f, 0.f, 0.f, 0.f, 0.f, 0.f, 0.f};
    float sw = 0.f;
#pragma unroll 4
    for (int e = beg + wid; e < end; e += 4) {
        int2 p = g_epack[e];                 // warp-uniform broadcast load
        float w = __int_as_float(p.y);
        uint4 d = *reinterpret_cast<const uint4*>(&xin[p.x * FD2 + lid * 4]);
        float2 f0 = __half22float2(*reinterpret_cast<__half2*>(&d.x));
        float2 f1 = __half22float2(*reinterpret_cast<__half2*>(&d.y));
        float2 f2 = __half22float2(*reinterpret_cast<__half2*>(&d.z));
        float2 f3 = __half22float2(*reinterpret_cast<__half2*>(&d.w));
        acc[0] += w * f0.x; acc[1] += w * f0.y;
        acc[2] += w * f1.x; acc[3] += w * f1.y;
        acc[4] += w * f2.x; acc[5] += w * f2.y;
        acc[6] += w * f3.x; acc[7] += w * f3.y;
        sw += w;
    }
#pragma unroll
    for (int k = 0; k < 8; k++) sred[wid][lid * 8 + k] = acc[k];
    if (lid == 0) swred[wid] = sw;
    __syncthreads();

    // combine: thread t handles features 2t, 2t+1 (one half2)
    int f2i = t;
    float a0 = 0.f, a1 = 0.f;
#pragma unroll
    for (int wv = 0; wv < 4; wv++) {
        float2 v = *reinterpret_cast<const float2*>(&sred[wv][2 * f2i]);
        a0 += v.x; a1 += v.y;
    }
    float swt = swred[0] + swred[1] + swred[2] + swred[3];
    float di = g_dinv[i];
    float selfw = di * di;
    float2 xv = __half22float2(xin[i * FD2 + f2i]);
    a0 += selfw * xv.x;
    a1 += selfw * xv.y;
    swt += selfw;
    if (FOLD) {
        float2 sc = *reinterpret_cast<const float2*>(&g_scale[f2i * 2]);
        float2 sh = *reinterpret_cast<const float2*>(&g_shift[f2i * 2]);
        a0 = sc.x * a0 + sh.x * swt;
        a1 = sc.y * a1 + sh.y * swt;
    }
    xout[i * FD2 + f2i] = __floats2half2_rn(a0, a1);
}

// ------- fused tensor-core GEMM: C = prelu(A @ W^T + b), + BN stats --------
// A = g_hx1 [N,256] fp16 row-major.  W fp16 [256,256] row-major (= B col-major).
// USE_W1 selects the __device__ weight array (no host-side symbol reference!).
// OUT_HALF: store fp16 to g_hx0 (layer-1) else fp32 g_x0 (layer-2).
template <bool USE_W1, bool OUT_HALF>
__global__ __launch_bounds__(256) void k_gemm_tc(const float* __restrict__ bias,
                                                 const float* __restrict__ pw) {
    // smem: mainloop A/B tiles overlap epilogue C staging
    __shared__ __align__(16) unsigned char raw[GBM * LDC * 4 + 16 * GBN * 4];
    __half* As = reinterpret_cast<__half*>(raw);                 // [128][LDA]
    __half* Bs = reinterpret_cast<__half*>(raw + GBM * LDA * 2); // [64][LDA]
    float*  Cs = reinterpret_cast<float*>(raw);                  // [128][LDC]
    float(*Red)[GBN] = reinterpret_cast<float(*)[GBN]>(raw + GBM * LDC * 4);

    const __half* __restrict__ A  = reinterpret_cast<const __half*>(g_hx1);
    const __half* __restrict__ hW = USE_W1 ? g_hw1 : g_hw2;

    int bm = blockIdx.x * GBM;
    int bn = blockIdx.y * GBN;
    int t  = threadIdx.x;
    int wid = t >> 5;
    int wm  = wid >> 1;          // 0..3 : warp row (32 rows each)
    int wn  = wid & 1;           // 0..1 : warp col (32 cols each)

    // A loader: 128 rows x 32 halves; thread: row = t>>1, 16 halves at (t&1)*16
    int arow = t >> 1;
    int aseg = (t & 1) * 16;
    int gm_ld = bm + arow;
    // B loader: 64 rows(n) x 32 halves(k); thread: n = t>>2, 8 halves at (t&3)*8
    int brow = t >> 2;
    int bseg = (t & 3) * 8;

    wmma::fragment<wmma::accumulator, 16, 16, 16, float> c[2][2];
#pragma unroll
    for (int i = 0; i < 2; i++)
#pragma unroll
        for (int j = 0; j < 2; j++) wmma::fill_fragment(c[i][j], 0.0f);

    for (int k0 = 0; k0 < FDIM; k0 += GBK) {
        // load A tile (zero-fill OOB rows)
        uint4 a0 = make_uint4(0u, 0u, 0u, 0u), a1 = a0;
        if (gm_ld < N_NODES) {
            const uint4* src = reinterpret_cast<const uint4*>(
                A + (size_t)gm_ld * FDIM + k0 + aseg);
            a0 = src[0]; a1 = src[1];
        }
        uint4* dstA = reinterpret_cast<uint4*>(&As[arow * LDA + aseg]);
        dstA[0] = a0; dstA[1] = a1;
        // load B tile (W rows bn..bn+63)
        const uint4* srcB = reinterpret_cast<const uint4*>(
            hW + (size_t)(bn + brow) * FDIM + k0 + bseg);
        *reinterpret_cast<uint4*>(&Bs[brow * LDA + bseg]) = srcB[0];
        __syncthreads();
#pragma unroll
        for (int kk = 0; kk < GBK; kk += 16) {
            wmma::fragment<wmma::matrix_a, 16, 16, 16, __half, wmma::row_major> af[2];
            wmma::fragment<wmma::matrix_b, 16, 16, 16, __half, wmma::col_major> bf[2];
#pragma unroll
            for (int i = 0; i < 2; i++)
                wmma::load_matrix_sync(af[i], &As[(wm * 32 + i * 16) * LDA + kk], LDA);
#pragma unroll
            for (int j = 0; j < 2; j++)
                wmma::load_matrix_sync(bf[j], &Bs[(wn * 32 + j * 16) * LDA + kk], LDA);
#pragma unroll
            for (int i = 0; i < 2; i++)
#pragma unroll
                for (int j = 0; j < 2; j++)
                    wmma::mma_sync(c[i][j], af[i], bf[j], c[i][j]);
        }
        __syncthreads();
    }

    // stage C to smem (overlaps As/Bs — separated by the final __syncthreads)
#pragma unroll
    for (int i = 0; i < 2; i++)
#pragma unroll
        for (int j = 0; j < 2; j++)
            wmma::store_matrix_sync(&Cs[(wm * 32 + i * 16) * LDC + wn * 32 + j * 16],
                                    c[i][j], LDC, wmma::mem_row_major);
    __syncthreads();

    // -------- epilogue: bias + PReLU + store + per-column partial stats ------
    int tn  = t & 15;          // 4-col group
    int tmg = t >> 4;          // 8-row group
    int n0 = bn + tn * 4;
    float4 bb  = *reinterpret_cast<const float4*>(&bias[n0]);
    float4 pwv = *reinterpret_cast<const float4*>(&pw[n0]);
    float cs[4]  = {0.f, 0.f, 0.f, 0.f};
    float cs2[4] = {0.f, 0.f, 0.f, 0.f};
#pragma unroll
    for (int r = 0; r < 8; r++) {
        int lr = tmg * 8 + r;
        int m  = bm + lr;
        float4 v = *reinterpret_cast<const float4*>(&Cs[lr * LDC + tn * 4]);
        v.x += bb.x; v.y += bb.y; v.z += bb.z; v.w += bb.w;
        v.x = (v.x >= 0.f) ? v.x : pwv.x * v.x;
        v.y = (v.y >= 0.f) ? v.y : pwv.y * v.y;
        v.z = (v.z >= 0.f) ? v.z : pwv.z * v.z;
        v.w = (v.w >= 0.f) ? v.w : pwv.w * v.w;
        if (m < N_NODES) {
            if (OUT_HALF) {
                __half2* dst = &g_hx0[m * FD2 + n0 / 2];
                dst[0] = __floats2half2_rn(v.x, v.y);
                dst[1] = __floats2half2_rn(v.z, v.w);
            } else {
                *reinterpret_cast<float4*>(&g_x0[(size_t)m * FDIM + n0]) = v;
            }
            cs[0] += v.x; cs[1] += v.y; cs[2] += v.z; cs[3] += v.w;
            cs2[0] += v.x * v.x; cs2[1] += v.y * v.y;
            cs2[2] += v.z * v.z; cs2[3] += v.w * v.w;
        }
    }

    // deterministic in-block column reduction (no atomics)
    int pbase = (blockIdx.y * GMB + blockIdx.x) * GBN;
#pragma unroll
    for (int i = 0; i < 4; i++) Red[tmg][tn * 4 + i] = cs[i];
    __syncthreads();
    if (t < GBN) {
        float s = 0.f;
#pragma unroll
        for (int r = 0; r < 16; r++) s += Red[r][t];
        g_gp1[pbase + t] = s;
    }
    __syncthreads();
#pragma unroll
    for (int i = 0; i < 4; i++) Red[tmg][tn * 4 + i] = cs2[i];
    __syncthreads();
    if (t < GBN) {
        float s = 0.f;
#pragma unroll
        for (int r = 0; r < 16; r++) s += Red[r][t];
        g_gp2[pbase + t] = s;
    }
}

// ---------------- BN finalize: reduce per-block partials -> scale/shift -----
__global__ void k_bn_finalize(const float* __restrict__ gamma,
                              const float* __restrict__ beta) {
    int f  = threadIdx.x;         // 256 threads, 1 block — deterministic order
    int by = f >> 6;
    int c  = f & 63;
    float s = 0.f, s2 = 0.f;
    for (int bx = 0; bx < GMB; bx++) {
        int idx = (by * GMB + bx) * GBN + c;
        s  += g_gp1[idx];
        s2 += g_gp2[idx];
    }
    float inv_n = 1.0f / (float)N_NODES;
    float mean = s * inv_n;
    float var  = s2 * inv_n - mean * mean;
    float sc   = gamma[f] * rsqrtf(var + BN_EPS);
    g_scale[f] = sc;
    g_shift[f] = beta[f] - mean * sc;
}

// ---------------- final BN apply: g_x0 -> d_out ----------------
__global__ void k_bn_apply_out(float* __restrict__ out_ext) {
    int i = blockIdx.x * blockDim.x + threadIdx.x;
    if (i >= NF4) return;
    int f4 = (i & 63) << 2;
    float4 v  = reinterpret_cast<const float4*>(g_x0)[i];
    float4 sc = *reinterpret_cast<const float4*>(&g_scale[f4]);
    float4 sh = *reinterpret_cast<const float4*>(&g_shift[f4]);
    v.x = v.x * sc.x + sh.x;
    v.y = v.y * sc.y + sh.y;
    v.z = v.z * sc.z + sh.z;
    v.w = v.w * sc.w + sh.w;
    reinterpret_cast<float4*>(out_ext)[i] = v;
}

// ---------------- launch ----------------
extern "C" void kernel_launch(void* const* d_in, const int* in_sizes, int n_in,
                              void* d_out, int out_size) {
    const float* cell  = (const float*)d_in[0];
    const float* sub   = (const float*)d_in[1];
    const int*   ei    = (const int*)  d_in[2];
    const float* ew    = (const float*)d_in[3];
    const float* W1    = (const float*)d_in[4];
    const float* b1    = (const float*)d_in[5];
    const float* W2    = (const float*)d_in[6];
    const float* b2    = (const float*)d_in[7];
    const float* pw    = (const float*)d_in[8];
    const float* gamma = (const float*)d_in[9];
    const float* beta  = (const float*)d_in[10];
    float* out = (float*)d_out;

    const int T = 256;
    // graph normalization setup (recomputed each call — deterministic work)
    k_init<<<(N_NODES + T - 1) / T, T>>>();
    k_concat<<<(NF4 + T - 1) / T, T>>>((const float4*)cell, (const float4*)sub);
    k_wcvt<<<(FDIM * FDIM + T - 1) / T, T>>>(W1, W2);
    k_degree<<<(E_TOT + T - 1) / T, T>>>(ei, ew);
    k_scan<<<1, 1024>>>();                 // dinv + colptr scan
    k_scatter<<<(E_TOT + T - 1) / T, T>>>(ei, ew);

    dim3 ggrid(GMB, FDIM / GBN);   // (235, 4)

    // ---- layer 1 (fp16 hops) ----
    k_spmm<true , false><<<N_NODES, 128>>>();   // hx0 -> hx1
    k_spmm<false, false><<<N_NODES, 128>>>();   // hx1 -> hx0
    k_spmm<true , false><<<N_NODES, 128>>>();   // hx0 -> hx1
    k_gemm_tc<true , true ><<<ggrid, T>>>(b1, pw);  // hx1 -> hx0 (fp16) + stats
    k_bn_finalize<<<1, FDIM>>>(gamma, beta);

    // ---- layer 2 (hop 1 folds layer-1 BN via linearity) ----
    k_spmm<true , true ><<<N_NODES, 128>>>();   // hx0 -> hx1 (BN folded)
    k_spmm<false, false><<<N_NODES, 128>>>();   // hx1 -> hx0
    k_spmm<true , false><<<N_NODES, 128>>>();   // hx0 -> hx1
    k_gemm_tc<false, false><<<ggrid, T>>>(b2, pw);  // hx1 -> g_x0 (fp32) + stats
    k_bn_finalize<<<1, FDIM>>>(gamma, beta);
    k_bn_apply_out<<<(NF4 + T - 1) / T, T>>>(out);  // g_x0 -> d_out
}

// round 8
// speedup vs baseline: 2.5724x; 1.1346x over previous
#include <cuda_runtime.h>
#include <cuda_fp16.h>
#include <mma.h>

using namespace nvcuda;

// Problem constants (fixed shapes for this problem instance)
#define N_CELL   66
#define N_NODES  30000
#define FDIM     256
#define FD2      128               // half2 per row
#define E_TOT    960000            // directed edges (both directions)
#define NF       (N_NODES * FDIM)  // 7,680,000
#define NF4      (NF / 4)
#define CELL4    ((N_CELL * FDIM) / 4)
#define BN_EPS   1e-5f
#define FPSCALE  16777216.0f       // 2^24 fixed-point for packed degree

// GEMM tiling
#define GBM 128
#define GBN 64
#define GBK 32
#define GMB 235                    // ceil(30000/128)
#define LDA 40                     // smem half stride (128 rows x 32 k, +8 pad)
#define LDC 72                     // smem float stride (128 rows x 64 n, +8 pad)

// ---------------- device scratch (static, no allocation) ----------------
__device__ __half2 g_hx0[N_NODES * FD2];   // fp16 feature ping
__device__ __half2 g_hx1[N_NODES * FD2];   // fp16 feature pong
__device__ float  g_x0[NF];                // fp32 GEMM2 output
__device__ __half g_hw1[FDIM * FDIM];      // fp16 W1
__device__ __half g_hw2[FDIM * FDIM];      // fp16 W2
__device__ unsigned long long g_packed[N_NODES];  // (count<<48)|fixed24.24 deg
__device__ float g_dinv[N_NODES];
__device__ int   g_colptr[N_NODES + 1];
__device__ int   g_cursor[N_NODES];
__device__ int2  g_epack[E_TOT];           // (src row, norm as bits)
__device__ float g_gp1[4 * GMB * GBN];     // per-block BN partial sums
__device__ float g_gp2[4 * GMB * GBN];     // per-block BN partial sumsq
__device__ float g_scale[FDIM];
__device__ float g_shift[FDIM];

// ---------------- setup kernels ----------------
__global__ void k_init() {
    int i = blockIdx.x * blockDim.x + threadIdx.x;
    // deg starts at 1.0 (self-loop weight), count 0
    if (i < N_NODES) g_packed[i] = (unsigned long long)(1u << 24);
}

// concat + fp16 quantize: hx0 = half(concat(cell, sub))
__global__ void k_concat(const float4* __restrict__ cell, const float4* __restrict__ sub) {
    int i = blockIdx.x * blockDim.x + threadIdx.x;
    if (i >= NF4) return;
    float4 v = (i < CELL4) ? cell[i] : sub[i - CELL4];
    g_hx0[i * 2]     = __floats2half2_rn(v.x, v.y);
    g_hx0[i * 2 + 1] = __floats2half2_rn(v.z, v.w);
}

// convert W1, W2 to fp16
__global__ void k_wcvt(const float* __restrict__ W1, const float* __restrict__ W2) {
    int i = blockIdx.x * blockDim.x + threadIdx.x;
    if (i < FDIM * FDIM) {
        g_hw1[i] = __float2half_rn(W1[i]);
        g_hw2[i] = __float2half_rn(W2[i]);
    }
}

// one packed 64-bit atomic per edge: count += 1, deg += fix24(ew)
__global__ void k_degree(const int* __restrict__ ei, const float* __restrict__ ew) {
    int e = blockIdx.x * blockDim.x + threadIdx.x;
    if (e >= E_TOT) return;
    int c = ei[E_TOT + e];             // target (col)
    unsigned long long add = (1ULL << 48) |
        (unsigned long long)__float2uint_rn(ew[e] * FPSCALE);
    atomicAdd(&g_packed[c], add);
}

// single-block: decode packed -> dinv, exclusive scan counts -> colptr/cursor
__global__ void k_scan() {
    __shared__ int sums[1024];
    int t = threadIdx.x;
    int base = t * 30;                 // 1024*30 = 30720 >= 30000
    int s = 0;
    int cnt_loc[30];
    for (int i = 0; i < 30; i++) {
        int idx = base + i;
        int c = 0;
        if (idx < N_NODES) {
            unsigned long long p = g_packed[idx];
            c = (int)(p >> 48);
            float deg = (float)(p & 0xFFFFFFFFFFFFULL) * (1.0f / FPSCALE);
            g_dinv[idx] = rsqrtf(deg);          // deg >= 1 always
            s += c;
        }
        cnt_loc[i] = c;
    }
    sums[t] = s;
    __syncthreads();
    for (int off = 1; off < 1024; off <<= 1) {
        int v = (t >= off) ? sums[t - off] : 0;
        __syncthreads();
        sums[t] += v;
        __syncthreads();
    }
    int run = (t == 0) ? 0 : sums[t - 1];
    for (int i = 0; i < 30; i++) {
        int idx = base + i;
        if (idx < N_NODES) {
            g_colptr[idx] = run;
            g_cursor[idx] = run;
            run += cnt_loc[i];
        }
    }
    if (t == 1023) g_colptr[N_NODES] = E_TOT;
}

// 2 edges per thread for MLP over the ATOMG latency
__global__ void k_scatter(const int* __restrict__ ei, const float* __restrict__ ew) {
    int e = (blockIdx.x * blockDim.x + threadIdx.x) * 2;
    if (e >= E_TOT) return;
    int2   r2 = *reinterpret_cast<const int2*>(&ei[e]);
    int2   c2 = *reinterpret_cast<const int2*>(&ei[E_TOT + e]);
    float2 w2 = *reinterpret_cast<const float2*>(&ew[e]);
    float dr0 = g_dinv[r2.x], dc0 = g_dinv[c2.x];
    float dr1 = g_dinv[r2.y], dc1 = g_dinv[c2.y];
    int pos0 = atomicAdd(&g_cursor[c2.x], 1);
    int pos1 = atomicAdd(&g_cursor[c2.y], 1);
    g_epack[pos0] = make_int2(r2.x, __float_as_int(dr0 * w2.x * dc0));
    g_epack[pos1] = make_int2(r2.y, __float_as_int(dr1 * w2.y * dc1));
}

// ---------------- SpMM: one WARP per destination node, zero sync ----------
// Lane owns 8 features (16B, LDG.128). Warp walks its node's full edge list.
// No smem, no barriers. 8 warps (8 nodes) per 256-thread block.
// SRC0: src = hx0, dst = hx1 (else swapped)
// FOLD: out = scale[f]*acc + shift[f]*sum_w   (BN applied via linearity)
template <bool SRC0, bool FOLD>
__global__ __launch_bounds__(256) void k_spmm() {
    const __half2* __restrict__ xin  = SRC0 ? g_hx0 : g_hx1;
    __half2*       __restrict__ xout = SRC0 ? g_hx1 : g_hx0;

    int node = blockIdx.x * 8 + (threadIdx.x >> 5);   // grid 3750 * 8 = 30000
    int lid  = threadIdx.x & 31;
    int beg = g_colptr[node];
    int end = g_colptr[node + 1];
    float di = g_dinv[node];
    float selfw = di * di;

    // self-loop term
    uint4 s = *reinterpret_cast<const uint4*>(&xin[node * FD2 + lid * 4]);
    float2 s0 = __half22float2(*reinterpret_cast<__half2*>(&s.x));
    float2 s1 = __half22float2(*reinterpret_cast<__half2*>(&s.y));
    float2 s2 = __half22float2(*reinterpret_cast<__half2*>(&s.z));
    float2 s3 = __half22float2(*reinterpret_cast<__half2*>(&s.w));
    float acc[8];
    acc[0] = selfw * s0.x; acc[1] = selfw * s0.y;
    acc[2] = selfw * s1.x; acc[3] = selfw * s1.y;
    acc[4] = selfw * s2.x; acc[5] = selfw * s2.y;
    acc[6] = selfw * s3.x; acc[7] = selfw * s3.y;
    float sw = selfw;   // only used when FOLD

#pragma unroll 4
    for (int e = beg; e < end; e++) {
        int2 p = g_epack[e];                 // warp-uniform, L1-resident
        float w = __int_as_float(p.y);
        uint4 d = *reinterpret_cast<const uint4*>(&xin[p.x * FD2 + lid * 4]);
        float2 f0 = __half22float2(*reinterpret_cast<__half2*>(&d.x));
        float2 f1 = __half22float2(*reinterpret_cast<__half2*>(&d.y));
        float2 f2 = __half22float2(*reinterpret_cast<__half2*>(&d.z));
        float2 f3 = __half22float2(*reinterpret_cast<__half2*>(&d.w));
        acc[0] += w * f0.x; acc[1] += w * f0.y;
        acc[2] += w * f1.x; acc[3] += w * f1.y;
        acc[4] += w * f2.x; acc[5] += w * f2.y;
        acc[6] += w * f3.x; acc[7] += w * f3.y;
        if (FOLD) sw += w;                   // lane-uniform, no reduction needed
    }

    if (FOLD) {
        int f0 = lid * 8;
        float4 sca = *reinterpret_cast<const float4*>(&g_scale[f0]);
        float4 scb = *reinterpret_cast<const float4*>(&g_scale[f0 + 4]);
        float4 sha = *reinterpret_cast<const float4*>(&g_shift[f0]);
        float4 shb = *reinterpret_cast<const float4*>(&g_shift[f0 + 4]);
        acc[0] = sca.x * acc[0] + sha.x * sw;
        acc[1] = sca.y * acc[1] + sha.y * sw;
        acc[2] = sca.z * acc[2] + sha.z * sw;
        acc[3] = sca.w * acc[3] + sha.w * sw;
        acc[4] = scb.x * acc[4] + shb.x * sw;
        acc[5] = scb.y * acc[5] + shb.y * sw;
        acc[6] = scb.z * acc[6] + shb.z * sw;
        acc[7] = scb.w * acc[7] + shb.w * sw;
    }

    uint4 o;
    *reinterpret_cast<__half2*>(&o.x) = __floats2half2_rn(acc[0], acc[1]);
    *reinterpret_cast<__half2*>(&o.y) = __floats2half2_rn(acc[2], acc[3]);
    *reinterpret_cast<__half2*>(&o.z) = __floats2half2_rn(acc[4], acc[5]);
    *reinterpret_cast<__half2*>(&o.w) = __floats2half2_rn(acc[6], acc[7]);
    *reinterpret_cast<uint4*>(&xout[node * FD2 + lid * 4]) = o;
}

// ------- fused tensor-core GEMM: C = prelu(A @ W^T + b), + BN stats --------
// A = g_hx1 [N,256] fp16 row-major.  W fp16 [256,256] row-major (= B col-major).
// USE_W1 selects the __device__ weight array (no host-side symbol reference!).
// OUT_HALF: store fp16 to g_hx0 (layer-1) else fp32 g_x0 (layer-2).
template <bool USE_W1, bool OUT_HALF>
__global__ __launch_bounds__(256) void k_gemm_tc(const float* __restrict__ bias,
                                                 const float* __restrict__ pw) {
    // smem: mainloop A/B tiles overlap epilogue C staging
    __shared__ __align__(16) unsigned char raw[GBM * LDC * 4 + 16 * GBN * 4];
    __half* As = reinterpret_cast<__half*>(raw);                 // [128][LDA]
    __half* Bs = reinterpret_cast<__half*>(raw + GBM * LDA * 2); // [64][LDA]
    float*  Cs = reinterpret_cast<float*>(raw);                  // [128][LDC]
    float(*Red)[GBN] = reinterpret_cast<float(*)[GBN]>(raw + GBM * LDC * 4);

    const __half* __restrict__ A  = reinterpret_cast<const __half*>(g_hx1);
    const __half* __restrict__ hW = USE_W1 ? g_hw1 : g_hw2;

    int bm = blockIdx.x * GBM;
    int bn = blockIdx.y * GBN;
    int t  = threadIdx.x;
    int wid = t >> 5;
    int wm  = wid >> 1;          // 0..3 : warp row (32 rows each)
    int wn  = wid & 1;           // 0..1 : warp col (32 cols each)

    // A loader: 128 rows x 32 halves; thread: row = t>>1, 16 halves at (t&1)*16
    int arow = t >> 1;
    int aseg = (t & 1) * 16;
    int gm_ld = bm + arow;
    // B loader: 64 rows(n) x 32 halves(k); thread: n = t>>2, 8 halves at (t&3)*8
    int brow = t >> 2;
    int bseg = (t & 3) * 8;

    wmma::fragment<wmma::accumulator, 16, 16, 16, float> c[2][2];
#pragma unroll
    for (int i = 0; i < 2; i++)
#pragma unroll
        for (int j = 0; j < 2; j++) wmma::fill_fragment(c[i][j], 0.0f);

    for (int k0 = 0; k0 < FDIM; k0 += GBK) {
        // load A tile (zero-fill OOB rows)
        uint4 a0 = make_uint4(0u, 0u, 0u, 0u), a1 = a0;
        if (gm_ld < N_NODES) {
            const uint4* src = reinterpret_cast<const uint4*>(
                A + (size_t)gm_ld * FDIM + k0 + aseg);
            a0 = src[0]; a1 = src[1];
        }
        uint4* dstA = reinterpret_cast<uint4*>(&As[arow * LDA + aseg]);
        dstA[0] = a0; dstA[1] = a1;
        // load B tile (W rows bn..bn+63)
        const uint4* srcB = reinterpret_cast<const uint4*>(
            hW + (size_t)(bn + brow) * FDIM + k0 + bseg);
        *reinterpret_cast<uint4*>(&Bs[brow * LDA + bseg]) = srcB[0];
        __syncthreads();
#pragma unroll
        for (int kk = 0; kk < GBK; kk += 16) {
            wmma::fragment<wmma::matrix_a, 16, 16, 16, __half, wmma::row_major> af[2];
            wmma::fragment<wmma::matrix_b, 16, 16, 16, __half, wmma::col_major> bf[2];
#pragma unroll
            for (int i = 0; i < 2; i++)
                wmma::load_matrix_sync(af[i], &As[(wm * 32 + i * 16) * LDA + kk], LDA);
#pragma unroll
            for (int j = 0; j < 2; j++)
                wmma::load_matrix_sync(bf[j], &Bs[(wn * 32 + j * 16) * LDA + kk], LDA);
#pragma unroll
            for (int i = 0; i < 2; i++)
#pragma unroll
                for (int j = 0; j < 2; j++)
                    wmma::mma_sync(c[i][j], af[i], bf[j], c[i][j]);
        }
        __syncthreads();
    }

    // stage C to smem (overlaps As/Bs — separated by the final __syncthreads)
#pragma unroll
    for (int i = 0; i < 2; i++)
#pragma unroll
        for (int j = 0; j < 2; j++)
            wmma::store_matrix_sync(&Cs[(wm * 32 + i * 16) * LDC + wn * 32 + j * 16],
                                    c[i][j], LDC, wmma::mem_row_major);
    __syncthreads();

    // -------- epilogue: bias + PReLU + store + per-column partial stats ------
    int tn  = t & 15;          // 4-col group
    int tmg = t >> 4;          // 8-row group
    int n0 = bn + tn * 4;
    float4 bb  = *reinterpret_cast<const float4*>(&bias[n0]);
    float4 pwv = *reinterpret_cast<const float4*>(&pw[n0]);
    float cs[4]  = {0.f, 0.f, 0.f, 0.f};
    float cs2[4] = {0.f, 0.f, 0.f, 0.f};
#pragma unroll
    for (int r = 0; r < 8; r++) {
        int lr = tmg * 8 + r;
        int m  = bm + lr;
        float4 v = *reinterpret_cast<const float4*>(&Cs[lr * LDC + tn * 4]);
        v.x += bb.x; v.y += bb.y; v.z += bb.z; v.w += bb.w;
        v.x = (v.x >= 0.f) ? v.x : pwv.x * v.x;
        v.y = (v.y >= 0.f) ? v.y : pwv.y * v.y;
        v.z = (v.z >= 0.f) ? v.z : pwv.z * v.z;
        v.w = (v.w >= 0.f) ? v.w : pwv.w * v.w;
        if (m < N_NODES) {
            if (OUT_HALF) {
                __half2* dst = &g_hx0[m * FD2 + n0 / 2];
                dst[0] = __floats2half2_rn(v.x, v.y);
                dst[1] = __floats2half2_rn(v.z, v.w);
            } else {
                *reinterpret_cast<float4*>(&g_x0[(size_t)m * FDIM + n0]) = v;
            }
            cs[0] += v.x; cs[1] += v.y; cs[2] += v.z; cs[3] += v.w;
            cs2[0] += v.x * v.x; cs2[1] += v.y * v.y;
            cs2[2] += v.z * v.z; cs2[3] += v.w * v.w;
        }
    }

    // deterministic in-block column reduction (no atomics)
    int pbase = (blockIdx.y * GMB + blockIdx.x) * GBN;
#pragma unroll
    for (int i = 0; i < 4; i++) Red[tmg][tn * 4 + i] = cs[i];
    __syncthreads();
    if (t < GBN) {
        float s = 0.f;
#pragma unroll
        for (int r = 0; r < 16; r++) s += Red[r][t];
        g_gp1[pbase + t] = s;
    }
    __syncthreads();
#pragma unroll
    for (int i = 0; i < 4; i++) Red[tmg][tn * 4 + i] = cs2[i];
    __syncthreads();
    if (t < GBN) {
        float s = 0.f;
#pragma unroll
        for (int r = 0; r < 16; r++) s += Red[r][t];
        g_gp2[pbase + t] = s;
    }
}

// ---------------- BN finalize: reduce per-block partials -> scale/shift -----
__global__ void k_bn_finalize(const float* __restrict__ gamma,
                              const float* __restrict__ beta) {
    int f  = threadIdx.x;         // 256 threads, 1 block — deterministic order
    int by = f >> 6;
    int c  = f & 63;
    float s = 0.f, s2 = 0.f;
    for (int bx = 0; bx < GMB; bx++) {
        int idx = (by * GMB + bx) * GBN + c;
        s  += g_gp1[idx];
        s2 += g_gp2[idx];
    }
    float inv_n = 1.0f / (float)N_NODES;
    float mean = s * inv_n;
    float var  = s2 * inv_n - mean * mean;
    float sc   = gamma[f] * rsqrtf(var + BN_EPS);
    g_scale[f] = sc;
    g_shift[f] = beta[f] - mean * sc;
}

// ---------------- final BN apply: g_x0 -> d_out ----------------
__global__ void k_bn_apply_out(float* __restrict__ out_ext) {
    int i = blockIdx.x * blockDim.x + threadIdx.x;
    if (i >= NF4) return;
    int f4 = (i & 63) << 2;
    float4 v  = reinterpret_cast<const float4*>(g_x0)[i];
    float4 sc = *reinterpret_cast<const float4*>(&g_scale[f4]);
    float4 sh = *reinterpret_cast<const float4*>(&g_shift[f4]);
    v.x = v.x * sc.x + sh.x;
    v.y = v.y * sc.y + sh.y;
    v.z = v.z * sc.z + sh.z;
    v.w = v.w * sc.w + sh.w;
    reinterpret_cast<float4*>(out_ext)[i] = v;
}

// ---------------- launch ----------------
extern "C" void kernel_launch(void* const* d_in, const int* in_sizes, int n_in,
                              void* d_out, int out_size) {
    const float* cell  = (const float*)d_in[0];
    const float* sub   = (const float*)d_in[1];
    const int*   ei    = (const int*)  d_in[2];
    const float* ew    = (const float*)d_in[3];
    const float* W1    = (const float*)d_in[4];
    const float* b1    = (const float*)d_in[5];
    const float* W2    = (const float*)d_in[6];
    const float* b2    = (const float*)d_in[7];
    const float* pw    = (const float*)d_in[8];
    const float* gamma = (const float*)d_in[9];
    const float* beta  = (const float*)d_in[10];
    float* out = (float*)d_out;

    const int T = 256;
    // graph normalization setup (recomputed each call — deterministic work)
    k_init<<<(N_NODES + T - 1) / T, T>>>();
    k_concat<<<(NF4 + T - 1) / T, T>>>((const float4*)cell, (const float4*)sub);
    k_wcvt<<<(FDIM * FDIM + T - 1) / T, T>>>(W1, W2);
    k_degree<<<(E_TOT + T - 1) / T, T>>>(ei, ew);
    k_scan<<<1, 1024>>>();                 // dinv + colptr scan
    k_scatter<<<(E_TOT / 2 + T - 1) / T, T>>>(ei, ew);

    dim3 ggrid(GMB, FDIM / GBN);   // (235, 4)
    const int SG = N_NODES / 8;    // 3750 blocks, 8 warps = 8 nodes each

    // ---- layer 1 (fp16 hops) ----
    k_spmm<true , false><<<SG, 256>>>();        // hx0 -> hx1
    k_spmm<false, false><<<SG, 256>>>();        // hx1 -> hx0
    k_spmm<true , false><<<SG, 256>>>();        // hx0 -> hx1
    k_gemm_tc<true , true ><<<ggrid, T>>>(b1, pw);  // hx1 -> hx0 (fp16) + stats
    k_bn_finalize<<<1, FDIM>>>(gamma, beta);

    // ---- layer 2 (hop 1 folds layer-1 BN via linearity) ----
    k_spmm<true , true ><<<SG, 256>>>();        // hx0 -> hx1 (BN folded)
    k_spmm<false, false><<<SG, 256>>>();        // hx1 -> hx0
    k_spmm<true , false><<<SG, 256>>>();        // hx0 -> hx1
    k_gemm_tc<false, false><<<ggrid, T>>>(b2, pw);  // hx1 -> g_x0 (fp32) + stats
    k_bn_finalize<<<1, FDIM>>>(gamma, beta);
    k_bn_apply_out<<<(NF4 + T - 1) / T, T>>>(out);  // g_x0 -> d_out
}

// round 9
// speedup vs baseline: 2.6094x; 1.0144x over previous
#include <cuda_runtime.h>
#include <cuda_fp16.h>
#include <mma.h>

using namespace nvcuda;

// Problem constants (fixed shapes for this problem instance)
#define N_CELL   66
#define N_NODES  30000
#define FDIM     256
#define FD2      128               // half2 per row
#define E_TOT    960000            // directed edges (both directions)
#define NF       (N_NODES * FDIM)  // 7,680,000
#define NF4      (NF / 4)
#define CELL4    ((N_CELL * FDIM) / 4)
#define BN_EPS   1e-5f
#define FPSCALE  16777216.0f       // 2^24 fixed-point for packed degree

// GEMM tiling
#define GBM 128
#define GBN 64
#define GBK 64
#define GMB 235                    // ceil(30000/128)
#define LDA 72                     // smem half stride (64 k + 8 pad)
#define LDC 72                     // smem float stride (64 n + 8 pad)

// ---------------- device scratch (static, no allocation) ----------------
__device__ __half2 g_hx0[N_NODES * FD2];   // fp16 feature ping
__device__ __half2 g_hx1[N_NODES * FD2];   // fp16 feature pong
__device__ float  g_x0[NF];                // fp32 GEMM2 output
__device__ __half g_hw1[FDIM * FDIM];      // fp16 W1
__device__ __half g_hw2[FDIM * FDIM];      // fp16 W2
__device__ unsigned long long g_packed[N_NODES];  // (count<<48)|fixed24.24 deg
__device__ float g_dinv[N_NODES];
__device__ int   g_colptr[N_NODES + 1];
__device__ int   g_cursor[N_NODES];
__device__ int2  g_epack[E_TOT];           // (src row, norm as bits)
__device__ float g_gp1[4 * GMB * GBN];     // per-block BN partial sums
__device__ float g_gp2[4 * GMB * GBN];     // per-block BN partial sumsq
__device__ float g_scale[FDIM];
__device__ float g_shift[FDIM];

// ---------------- setup kernels ----------------
// fused: packed-degree init (i < N_NODES) + W1/W2 fp16 convert (i < 64K)
__global__ void k_setup(const float* __restrict__ W1, const float* __restrict__ W2) {
    int i = blockIdx.x * blockDim.x + threadIdx.x;
    if (i < N_NODES) g_packed[i] = (unsigned long long)(1u << 24); // deg=1.0, cnt=0
    if (i < FDIM * FDIM) {
        g_hw1[i] = __float2half_rn(W1[i]);
        g_hw2[i] = __float2half_rn(W2[i]);
    }
}

// concat + fp16 quantize: hx0 = half(concat(cell, sub))
__global__ void k_concat(const float4* __restrict__ cell, const float4* __restrict__ sub) {
    int i = blockIdx.x * blockDim.x + threadIdx.x;
    if (i >= NF4) return;
    float4 v = (i < CELL4) ? cell[i] : sub[i - CELL4];
    g_hx0[i * 2]     = __floats2half2_rn(v.x, v.y);
    g_hx0[i * 2 + 1] = __floats2half2_rn(v.z, v.w);
}

// one packed 64-bit atomic per edge: count += 1, deg += fix24(ew)
__global__ void k_degree(const int* __restrict__ ei, const float* __restrict__ ew) {
    int e = blockIdx.x * blockDim.x + threadIdx.x;
    if (e >= E_TOT) return;
    int c = ei[E_TOT + e];             // target (col)
    unsigned long long add = (1ULL << 48) |
        (unsigned long long)__float2uint_rn(ew[e] * FPSCALE);
    atomicAdd(&g_packed[c], add);
}

// single-block: decode packed -> dinv, exclusive scan counts -> colptr/cursor
__global__ void k_scan() {
    __shared__ int sums[1024];
    int t = threadIdx.x;
    int base = t * 30;                 // 1024*30 = 30720 >= 30000
    int s = 0;
    int cnt_loc[30];
    for (int i = 0; i < 30; i++) {
        int idx = base + i;
        int c = 0;
        if (idx < N_NODES) {
            unsigned long long p = g_packed[idx];
            c = (int)(p >> 48);
            float deg = (float)(p & 0xFFFFFFFFFFFFULL) * (1.0f / FPSCALE);
            g_dinv[idx] = rsqrtf(deg);          // deg >= 1 always
            s += c;
        }
        cnt_loc[i] = c;
    }
    sums[t] = s;
    __syncthreads();
    for (int off = 1; off < 1024; off <<= 1) {
        int v = (t >= off) ? sums[t - off] : 0;
        __syncthreads();
        sums[t] += v;
        __syncthreads();
    }
    int run = (t == 0) ? 0 : sums[t - 1];
    for (int i = 0; i < 30; i++) {
        int idx = base + i;
        if (idx < N_NODES) {
            g_colptr[idx] = run;
            g_cursor[idx] = run;
            run += cnt_loc[i];
        }
    }
    if (t == 1023) g_colptr[N_NODES] = E_TOT;
}

// 4 edges per thread for MLP over the ATOMG latency
__global__ void k_scatter(const int* __restrict__ ei, const float* __restrict__ ew) {
    int e = (blockIdx.x * blockDim.x + threadIdx.x) * 4;
    if (e >= E_TOT) return;
    int4   r4 = *reinterpret_cast<const int4*>(&ei[e]);
    int4   c4 = *reinterpret_cast<const int4*>(&ei[E_TOT + e]);
    float4 w4 = *reinterpret_cast<const float4*>(&ew[e]);
    float n0 = g_dinv[r4.x] * w4.x * g_dinv[c4.x];
    float n1 = g_dinv[r4.y] * w4.y * g_dinv[c4.y];
    float n2 = g_dinv[r4.z] * w4.z * g_dinv[c4.z];
    float n3 = g_dinv[r4.w] * w4.w * g_dinv[c4.w];
    int p0 = atomicAdd(&g_cursor[c4.x], 1);
    int p1 = atomicAdd(&g_cursor[c4.y], 1);
    int p2 = atomicAdd(&g_cursor[c4.z], 1);
    int p3 = atomicAdd(&g_cursor[c4.w], 1);
    g_epack[p0] = make_int2(r4.x, __float_as_int(n0));
    g_epack[p1] = make_int2(r4.y, __float_as_int(n1));
    g_epack[p2] = make_int2(r4.z, __float_as_int(n2));
    g_epack[p3] = make_int2(r4.w, __float_as_int(n3));
}

// ---------------- SpMM: one WARP per destination node, zero sync ----------
// Lane owns 8 features (16B, LDG.128). Warp walks its node's full edge list.
// SRC0: src = hx0, dst = hx1 (else swapped)
// FOLD: out = scale[f]*acc + shift[f]*sum_w   (BN applied via linearity)
template <bool SRC0, bool FOLD>
__global__ __launch_bounds__(256) void k_spmm() {
    const __half2* __restrict__ xin  = SRC0 ? g_hx0 : g_hx1;
    __half2*       __restrict__ xout = SRC0 ? g_hx1 : g_hx0;

    int node = blockIdx.x * 8 + (threadIdx.x >> 5);   // grid 3750 * 8 = 30000
    int lid  = threadIdx.x & 31;
    int beg = g_colptr[node];
    int end = g_colptr[node + 1];
    float di = g_dinv[node];
    float selfw = di * di;

    // self-loop term
    uint4 s = *reinterpret_cast<const uint4*>(&xin[node * FD2 + lid * 4]);
    float2 s0 = __half22float2(*reinterpret_cast<__half2*>(&s.x));
    float2 s1 = __half22float2(*reinterpret_cast<__half2*>(&s.y));
    float2 s2 = __half22float2(*reinterpret_cast<__half2*>(&s.z));
    float2 s3 = __half22float2(*reinterpret_cast<__half2*>(&s.w));
    float acc[8];
    acc[0] = selfw * s0.x; acc[1] = selfw * s0.y;
    acc[2] = selfw * s1.x; acc[3] = selfw * s1.y;
    acc[4] = selfw * s2.x; acc[5] = selfw * s2.y;
    acc[6] = selfw * s3.x; acc[7] = selfw * s3.y;
    float sw = selfw;   // only used when FOLD

#pragma unroll 8
    for (int e = beg; e < end; e++) {
        int2 p = g_epack[e];                 // warp-uniform, L1-resident
        float w = __int_as_float(p.y);
        uint4 d = *reinterpret_cast<const uint4*>(&xin[p.x * FD2 + lid * 4]);
        float2 f0 = __half22float2(*reinterpret_cast<__half2*>(&d.x));
        float2 f1 = __half22float2(*reinterpret_cast<__half2*>(&d.y));
        float2 f2 = __half22float2(*reinterpret_cast<__half2*>(&d.z));
        float2 f3 = __half22float2(*reinterpret_cast<__half2*>(&d.w));
        acc[0] += w * f0.x; acc[1] += w * f0.y;
        acc[2] += w * f1.x; acc[3] += w * f1.y;
        acc[4] += w * f2.x; acc[5] += w * f2.y;
        acc[6] += w * f3.x; acc[7] += w * f3.y;
        if (FOLD) sw += w;                   // lane-uniform, no reduction needed
    }

    if (FOLD) {
        int f0 = lid * 8;
        float4 sca = *reinterpret_cast<const float4*>(&g_scale[f0]);
        float4 scb = *reinterpret_cast<const float4*>(&g_scale[f0 + 4]);
        float4 sha = *reinterpret_cast<const float4*>(&g_shift[f0]);
        float4 shb = *reinterpret_cast<const float4*>(&g_shift[f0 + 4]);
        acc[0] = sca.x * acc[0] + sha.x * sw;
        acc[1] = sca.y * acc[1] + sha.y * sw;
        acc[2] = sca.z * acc[2] + sha.z * sw;
        acc[3] = sca.w * acc[3] + sha.w * sw;
        acc[4] = scb.x * acc[4] + shb.x * sw;
        acc[5] = scb.y * acc[5] + shb.y * sw;
        acc[6] = scb.z * acc[6] + shb.z * sw;
        acc[7] = scb.w * acc[7] + shb.w * sw;
    }

    uint4 o;
    *reinterpret_cast<__half2*>(&o.x) = __floats2half2_rn(acc[0], acc[1]);
    *reinterpret_cast<__half2*>(&o.y) = __floats2half2_rn(acc[2], acc[3]);
    *reinterpret_cast<__half2*>(&o.z) = __floats2half2_rn(acc[4], acc[5]);
    *reinterpret_cast<__half2*>(&o.w) = __floats2half2_rn(acc[6], acc[7]);
    *reinterpret_cast<uint4*>(&xout[node * FD2 + lid * 4]) = o;
}

// ------- fused tensor-core GEMM: C = prelu(A @ W^T + b), + BN stats --------
// A = g_hx1 [N,256] fp16 row-major.  W fp16 [256,256] row-major (= B col-major).
// USE_W1 selects the __device__ weight array; OUT_HALF -> g_hx0 else g_x0.
template <bool USE_W1, bool OUT_HALF>
__global__ __launch_bounds__(256) void k_gemm_tc(const float* __restrict__ bias,
                                                 const float* __restrict__ pw) {
    // smem: mainloop A/B tiles overlap epilogue C staging
    __shared__ __align__(16) unsigned char raw[GBM * LDC * 4 + 16 * GBN * 4];
    __half* As = reinterpret_cast<__half*>(raw);                 // [128][LDA]
    __half* Bs = reinterpret_cast<__half*>(raw + GBM * LDA * 2); // [64][LDA]
    float*  Cs = reinterpret_cast<float*>(raw);                  // [128][LDC]
    float(*Red)[GBN] = reinterpret_cast<float(*)[GBN]>(raw + GBM * LDC * 4);

    const __half* __restrict__ A  = reinterpret_cast<const __half*>(g_hx1);
    const __half* __restrict__ hW = USE_W1 ? g_hw1 : g_hw2;

    int bm = blockIdx.x * GBM;
    int bn = blockIdx.y * GBN;
    int t  = threadIdx.x;
    int wid = t >> 5;
    int wm  = wid >> 1;          // 0..3 : warp row (32 rows each)
    int wn  = wid & 1;           // 0..1 : warp col (32 cols each)

    // A loader: 128 rows x 64 halves; thread: row = t>>1, 32 halves at (t&1)*32
    int arow = t >> 1;
    int aseg = (t & 1) * 32;
    int gm_ld = bm + arow;
    // B loader: 64 rows(n) x 64 halves(k); thread: n = t>>2, 16 halves at (t&3)*16
    int brow = t >> 2;
    int bseg = (t & 3) * 16;

    wmma::fragment<wmma::accumulator, 16, 16, 16, float> c[2][2];
#pragma unroll
    for (int i = 0; i < 2; i++)
#pragma unroll
        for (int j = 0; j < 2; j++) wmma::fill_fragment(c[i][j], 0.0f);

    for (int k0 = 0; k0 < FDIM; k0 += GBK) {
        // load A tile (zero-fill OOB rows): 4x uint4 per thread
        uint4 a0 = make_uint4(0u,0u,0u,0u), a1 = a0, a2 = a0, a3 = a0;
        if (gm_ld < N_NODES) {
            const uint4* src = reinterpret_cast<const uint4*>(
                A + (size_t)gm_ld * FDIM + k0 + aseg);
            a0 = src[0]; a1 = src[1]; a2 = src[2]; a3 = src[3];
        }
        uint4* dstA = reinterpret_cast<uint4*>(&As[arow * LDA + aseg]);
        dstA[0] = a0; dstA[1] = a1; dstA[2] = a2; dstA[3] = a3;
        // load B tile (W rows bn..bn+63): 2x uint4 per thread
        const uint4* srcB = reinterpret_cast<const uint4*>(
            hW + (size_t)(bn + brow) * FDIM + k0 + bseg);
        uint4 b0 = srcB[0], b1 = srcB[1];
        uint4* dstB = reinterpret_cast<uint4*>(&Bs[brow * LDA + bseg]);
        dstB[0] = b0; dstB[1] = b1;
        __syncthreads();
#pragma unroll
        for (int kk = 0; kk < GBK; kk += 16) {
            wmma::fragment<wmma::matrix_a, 16, 16, 16, __half, wmma::row_major> af[2];
            wmma::fragment<wmma::matrix_b, 16, 16, 16, __half, wmma::col_major> bf[2];
#pragma unroll
            for (int i = 0; i < 2; i++)
                wmma::load_matrix_sync(af[i], &As[(wm * 32 + i * 16) * LDA + kk], LDA);
#pragma unroll
            for (int j = 0; j < 2; j++)
                wmma::load_matrix_sync(bf[j], &Bs[(wn * 32 + j * 16) * LDA + kk], LDA);
#pragma unroll
            for (int i = 0; i < 2; i++)
#pragma unroll
                for (int j = 0; j < 2; j++)
                    wmma::mma_sync(c[i][j], af[i], bf[j], c[i][j]);
        }
        __syncthreads();
    }

    // stage C to smem (overlaps As/Bs — separated by the final __syncthreads)
#pragma unroll
    for (int i = 0; i < 2; i++)
#pragma unroll
        for (int j = 0; j < 2; j++)
            wmma::store_matrix_sync(&Cs[(wm * 32 + i * 16) * LDC + wn * 32 + j * 16],
                                    c[i][j], LDC, wmma::mem_row_major);
    __syncthreads();

    // -------- epilogue: bias + PReLU + store + per-column partial stats ------
    int tn  = t & 15;          // 4-col group
    int tmg = t >> 4;          // 8-row group
    int n0 = bn + tn * 4;
    float4 bb  = *reinterpret_cast<const float4*>(&bias[n0]);
    float4 pwv = *reinterpret_cast<const float4*>(&pw[n0]);
    float cs[4]  = {0.f, 0.f, 0.f, 0.f};
    float cs2[4] = {0.f, 0.f, 0.f, 0.f};
#pragma unroll
    for (int r = 0; r < 8; r++) {
        int lr = tmg * 8 + r;
        int m  = bm + lr;
        float4 v = *reinterpret_cast<const float4*>(&Cs[lr * LDC + tn * 4]);
        v.x += bb.x; v.y += bb.y; v.z += bb.z; v.w += bb.w;
        v.x = (v.x >= 0.f) ? v.x : pwv.x * v.x;
        v.y = (v.y >= 0.f) ? v.y : pwv.y * v.y;
        v.z = (v.z >= 0.f) ? v.z : pwv.z * v.z;
        v.w = (v.w >= 0.f) ? v.w : pwv.w * v.w;
        if (m < N_NODES) {
            if (OUT_HALF) {
                __half2* dst = &g_hx0[m * FD2 + n0 / 2];
                dst[0] = __floats2half2_rn(v.x, v.y);
                dst[1] = __floats2half2_rn(v.z, v.w);
            } else {
                *reinterpret_cast<float4*>(&g_x0[(size_t)m * FDIM + n0]) = v;
            }
            cs[0] += v.x; cs[1] += v.y; cs[2] += v.z; cs[3] += v.w;
            cs2[0] += v.x * v.x; cs2[1] += v.y * v.y;
            cs2[2] += v.z * v.z; cs2[3] += v.w * v.w;
        }
    }

    // deterministic in-block column reduction (no atomics)
    int pbase = (blockIdx.y * GMB + blockIdx.x) * GBN;
#pragma unroll
    for (int i = 0; i < 4; i++) Red[tmg][tn * 4 + i] = cs[i];
    __syncthreads();
    if (t < GBN) {
        float s = 0.f;
#pragma unroll
        for (int r = 0; r < 16; r++) s += Red[r][t];
        g_gp1[pbase + t] = s;
    }
    __syncthreads();
#pragma unroll
    for (int i = 0; i < 4; i++) Red[tmg][tn * 4 + i] = cs2[i];
    __syncthreads();
    if (t < GBN) {
        float s = 0.f;
#pragma unroll
        for (int r = 0; r < 16; r++) s += Red[r][t];
        g_gp2[pbase + t] = s;
    }
}

// ------- BN finalize: 1024 threads, 4-way chunked, fixed combine order -----
__global__ void k_bn_finalize(const float* __restrict__ gamma,
                              const float* __restrict__ beta) {
    __shared__ float p1[4][FDIM];
    __shared__ float p2[4][FDIM];
    int f     = threadIdx.x & 255;
    int chunk = threadIdx.x >> 8;      // 0..3
    int by = f >> 6;
    int c  = f & 63;
    int bx0 = chunk * 59;
    int bx1 = (bx0 + 59 < GMB) ? bx0 + 59 : GMB;
    float s = 0.f, s2 = 0.f;
    for (int bx = bx0; bx < bx1; bx++) {
        int idx = (by * GMB + bx) * GBN + c;
        s  += g_gp1[idx];
        s2 += g_gp2[idx];
    }
    p1[chunk][f] = s;
    p2[chunk][f] = s2;
    __syncthreads();
    if (threadIdx.x < FDIM) {
        float S  = p1[0][f] + p1[1][f] + p1[2][f] + p1[3][f];   // fixed order
        float S2 = p2[0][f] + p2[1][f] + p2[2][f] + p2[3][f];
        float inv_n = 1.0f / (float)N_NODES;
        float mean = S * inv_n;
        float var  = S2 * inv_n - mean * mean;
        float sc   = gamma[f] * rsqrtf(var + BN_EPS);
        g_scale[f] = sc;
        g_shift[f] = beta[f] - mean * sc;
    }
}

// ---------------- final BN apply: g_x0 -> d_out ----------------
__global__ void k_bn_apply_out(float* __restrict__ out_ext) {
    int i = blockIdx.x * blockDim.x + threadIdx.x;
    if (i >= NF4) return;
    int f4 = (i & 63) << 2;
    float4 v  = reinterpret_cast<const float4*>(g_x0)[i];
    float4 sc = *reinterpret_cast<const float4*>(&g_scale[f4]);
    float4 sh = *reinterpret_cast<const float4*>(&g_shift[f4]);
    v.x = v.x * sc.x + sh.x;
    v.y = v.y * sc.y + sh.y;
    v.z = v.z * sc.z + sh.z;
    v.w = v.w * sc.w + sh.w;
    reinterpret_cast<float4*>(out_ext)[i] = v;
}

// ---------------- launch ----------------
extern "C" void kernel_launch(void* const* d_in, const int* in_sizes, int n_in,
                              void* d_out, int out_size) {
    const float* cell  = (const float*)d_in[0];
    const float* sub   = (const float*)d_in[1];
    const int*   ei    = (const int*)  d_in[2];
    const float* ew    = (const float*)d_in[3];
    const float* W1    = (const float*)d_in[4];
    const float* b1    = (const float*)d_in[5];
    const float* W2    = (const float*)d_in[6];
    const float* b2    = (const float*)d_in[7];
    const float* pw    = (const float*)d_in[8];
    const float* gamma = (const float*)d_in[9];
    const float* beta  = (const float*)d_in[10];
    float* out = (float*)d_out;

    const int T = 256;
    // graph normalization setup (recomputed each call — deterministic work)
    k_setup<<<(FDIM * FDIM + T - 1) / T, T>>>(W1, W2);  // packed init + W cvt
    k_concat<<<(NF4 + T - 1) / T, T>>>((const float4*)cell, (const float4*)sub);
    k_degree<<<(E_TOT + T - 1) / T, T>>>(ei, ew);
    k_scan<<<1, 1024>>>();                 // dinv + colptr scan
    k_scatter<<<(E_TOT / 4 + T - 1) / T, T>>>(ei, ew);

    dim3 ggrid(GMB, FDIM / GBN);   // (235, 4)
    const int SG = N_NODES / 8;    // 3750 blocks, 8 warps = 8 nodes each

    // ---- layer 1 (fp16 hops) ----
    k_spmm<true , false><<<SG, 256>>>();        // hx0 -> hx1
    k_spmm<false, false><<<SG, 256>>>();        // hx1 -> hx0
    k_spmm<true , false><<<SG, 256>>>();        // hx0 -> hx1
    k_gemm_tc<true , true ><<<ggrid, T>>>(b1, pw);  // hx1 -> hx0 (fp16) + stats
    k_bn_finalize<<<1, 1024>>>(gamma, beta);

    // ---- layer 2 (hop 1 folds layer-1 BN via linearity) ----
    k_spmm<true , true ><<<SG, 256>>>();        // hx0 -> hx1 (BN folded)
    k_spmm<false, false><<<SG, 256>>>();        // hx1 -> hx0
    k_spmm<true , false><<<SG, 256>>>();        // hx0 -> hx1
    k_gemm_tc<false, false><<<ggrid, T>>>(b2, pw);  // hx1 -> g_x0 (fp32) + stats
    k_bn_finalize<<<1, 1024>>>(gamma, beta);
    k_bn_apply_out<<<(NF4 + T - 1) / T, T>>>(out);  // g_x0 -> d_out
}

// round 10
// speedup vs baseline: 3.0147x; 1.1553x over previous
#include <cuda_runtime.h>
#include <cuda_fp16.h>
#include <mma.h>

using namespace nvcuda;

// Problem constants (fixed shapes for this problem instance)
#define N_CELL   66
#define N_NODES  30000
#define FDIM     256
#define FD2      128               // half2 per row
#define E_TOT    960000            // directed edges (both directions)
#define NF       (N_NODES * FDIM)  // 7,680,000
#define NF4      (NF / 4)
#define CELL4    ((N_CELL * FDIM) / 4)
#define BN_EPS   1e-5f
#define FPSCALE  16777216.0f       // 2^24 fixed-point for packed degree
#define NBLK     118               // ceil(30000/256) scan blocks

// GEMM tiling
#define GBM 128
#define GBN 64
#define GBK 64
#define GMB 235                    // ceil(30000/128)
#define LDA 72                     // smem half stride (64 k + 8 pad)
#define LDC 72                     // smem float stride (64 n + 8 pad)

// ---------------- device scratch (static, no allocation) ----------------
__device__ __half2 g_hx0[N_NODES * FD2];   // fp16 feature ping
__device__ __half2 g_hx1[N_NODES * FD2];   // fp16 feature pong
__device__ float  g_x0[NF];                // fp32 GEMM2 output
__device__ __half g_hw1[FDIM * FDIM];      // fp16 W1
__device__ __half g_hw2[FDIM * FDIM];      // fp16 W2
__device__ unsigned long long g_packed[N_NODES];  // (count<<48)|fixed24.24 deg
__device__ float g_dinv[N_NODES];
__device__ int   g_colptr[N_NODES + 1];
__device__ int   g_cursor[N_NODES];
__device__ int   g_bsum[NBLK];
__device__ int   g_boff[NBLK];
__device__ int2  g_epack[E_TOT];           // (src row, norm as bits)
__device__ float g_gp1[4 * GMB * GBN];     // per-block BN partial sums
__device__ float g_gp2[4 * GMB * GBN];     // per-block BN partial sumsq
__device__ float g_scale[FDIM];
__device__ float g_shift[FDIM];

// ---------------- setup kernels ----------------
// fused: packed-degree init (i < N_NODES) + W1/W2 fp16 convert (i < 64K)
__global__ void k_setup(const float* __restrict__ W1, const float* __restrict__ W2) {
    int i = blockIdx.x * blockDim.x + threadIdx.x;
    if (i < N_NODES) g_packed[i] = (unsigned long long)(1u << 24); // deg=1.0, cnt=0
    if (i < FDIM * FDIM) {
        g_hw1[i] = __float2half_rn(W1[i]);
        g_hw2[i] = __float2half_rn(W2[i]);
    }
}

// concat + fp16 quantize: hx0 = half(concat(cell, sub))
__global__ void k_concat(const float4* __restrict__ cell, const float4* __restrict__ sub) {
    int i = blockIdx.x * blockDim.x + threadIdx.x;
    if (i >= NF4) return;
    float4 v = (i < CELL4) ? cell[i] : sub[i - CELL4];
    g_hx0[i * 2]     = __floats2half2_rn(v.x, v.y);
    g_hx0[i * 2 + 1] = __floats2half2_rn(v.z, v.w);
}

// one packed 64-bit atomic per edge: count += 1, deg += fix24(ew)
__global__ void k_degree(const int* __restrict__ ei, const float* __restrict__ ew) {
    int e = blockIdx.x * blockDim.x + threadIdx.x;
    if (e >= E_TOT) return;
    int c = ei[E_TOT + e];             // target (col)
    unsigned long long add = (1ULL << 48) |
        (unsigned long long)__float2uint_rn(ew[e] * FPSCALE);
    atomicAdd(&g_packed[c], add);
}

// ---- hierarchical scan stage A: decode + per-block exclusive scan --------
__global__ __launch_bounds__(256) void k_scan_a() {
    __shared__ int sm[256];
    int t = threadIdx.x;
    int i = blockIdx.x * 256 + t;
    int c = 0;
    if (i < N_NODES) {
        unsigned long long p = g_packed[i];
        c = (int)(p >> 48);
        float deg = (float)(p & 0xFFFFFFFFFFFFULL) * (1.0f / FPSCALE);
        g_dinv[i] = rsqrtf(deg);           // deg >= 1 always
    }
    sm[t] = c;
    __syncthreads();
#pragma unroll
    for (int off = 1; off < 256; off <<= 1) {
        int v = (t >= off) ? sm[t - off] : 0;
        __syncthreads();
        sm[t] += v;
        __syncthreads();
    }
    if (i < N_NODES) g_colptr[i] = sm[t] - c;        // local exclusive prefix
    if (t == 255) g_bsum[blockIdx.x] = sm[255];      // block total
}

// ---- stage B: scan the 118 block totals -----------------------------------
__global__ void k_scan_b() {
    __shared__ int sm[128];
    int t = threadIdx.x;
    int v = (t < NBLK) ? g_bsum[t] : 0;
    sm[t] = v;
    __syncthreads();
#pragma unroll
    for (int off = 1; off < 128; off <<= 1) {
        int u = (t >= off) ? sm[t - off] : 0;
        __syncthreads();
        sm[t] += u;
        __syncthreads();
    }
    if (t < NBLK) g_boff[t] = sm[t] - v;             // exclusive block offset
    if (t == 127) g_colptr[N_NODES] = E_TOT;
}

// ---- stage C: apply block offsets -----------------------------------------
__global__ __launch_bounds__(256) void k_scan_c() {
    int i = blockIdx.x * 256 + threadIdx.x;
    if (i < N_NODES) {
        int v = g_colptr[i] + g_boff[blockIdx.x];
        g_colptr[i] = v;
        g_cursor[i] = v;
    }
}

// 4 edges per thread for MLP over the ATOMG latency
__global__ void k_scatter(const int* __restrict__ ei, const float* __restrict__ ew) {
    int e = (blockIdx.x * blockDim.x + threadIdx.x) * 4;
    if (e >= E_TOT) return;
    int4   r4 = *reinterpret_cast<const int4*>(&ei[e]);
    int4   c4 = *reinterpret_cast<const int4*>(&ei[E_TOT + e]);
    float4 w4 = *reinterpret_cast<const float4*>(&ew[e]);
    float n0 = g_dinv[r4.x] * w4.x * g_dinv[c4.x];
    float n1 = g_dinv[r4.y] * w4.y * g_dinv[c4.y];
    float n2 = g_dinv[r4.z] * w4.z * g_dinv[c4.z];
    float n3 = g_dinv[r4.w] * w4.w * g_dinv[c4.w];
    int p0 = atomicAdd(&g_cursor[c4.x], 1);
    int p1 = atomicAdd(&g_cursor[c4.y], 1);
    int p2 = atomicAdd(&g_cursor[c4.z], 1);
    int p3 = atomicAdd(&g_cursor[c4.w], 1);
    g_epack[p0] = make_int2(r4.x, __float_as_int(n0));
    g_epack[p1] = make_int2(r4.y, __float_as_int(n1));
    g_epack[p2] = make_int2(r4.z, __float_as_int(n2));
    g_epack[p3] = make_int2(r4.w, __float_as_int(n3));
}

// ---------------- SpMM: one WARP per destination node, zero sync ----------
// Lane owns 8 features (16B, LDG.128). Warp walks its node's full edge list.
// SRC0: src = hx0, dst = hx1 (else swapped)
// FOLD: out = scale[f]*acc + shift[f]*sum_w   (BN applied via linearity)
template <bool SRC0, bool FOLD>
__global__ __launch_bounds__(256) void k_spmm() {
    const __half2* __restrict__ xin  = SRC0 ? g_hx0 : g_hx1;
    __half2*       __restrict__ xout = SRC0 ? g_hx1 : g_hx0;

    int node = blockIdx.x * 8 + (threadIdx.x >> 5);   // grid 3750 * 8 = 30000
    int lid  = threadIdx.x & 31;
    int beg = g_colptr[node];
    int end = g_colptr[node + 1];
    float di = g_dinv[node];
    float selfw = di * di;

    // self-loop term
    uint4 s = *reinterpret_cast<const uint4*>(&xin[node * FD2 + lid * 4]);
    float2 s0 = __half22float2(*reinterpret_cast<__half2*>(&s.x));
    float2 s1 = __half22float2(*reinterpret_cast<__half2*>(&s.y));
    float2 s2 = __half22float2(*reinterpret_cast<__half2*>(&s.z));
    float2 s3 = __half22float2(*reinterpret_cast<__half2*>(&s.w));
    float acc[8];
    acc[0] = selfw * s0.x; acc[1] = selfw * s0.y;
    acc[2] = selfw * s1.x; acc[3] = selfw * s1.y;
    acc[4] = selfw * s2.x; acc[5] = selfw * s2.y;
    acc[6] = selfw * s3.x; acc[7] = selfw * s3.y;
    float sw = selfw;   // only used when FOLD

#pragma unroll 8
    for (int e = beg; e < end; e++) {
        int2 p = g_epack[e];                 // warp-uniform, L1-resident
        float w = __int_as_float(p.y);
        uint4 d = *reinterpret_cast<const uint4*>(&xin[p.x * FD2 + lid * 4]);
        float2 f0 = __half22float2(*reinterpret_cast<__half2*>(&d.x));
        float2 f1 = __half22float2(*reinterpret_cast<__half2*>(&d.y));
        float2 f2 = __half22float2(*reinterpret_cast<__half2*>(&d.z));
        float2 f3 = __half22float2(*reinterpret_cast<__half2*>(&d.w));
        acc[0] += w * f0.x; acc[1] += w * f0.y;
        acc[2] += w * f1.x; acc[3] += w * f1.y;
        acc[4] += w * f2.x; acc[5] += w * f2.y;
        acc[6] += w * f3.x; acc[7] += w * f3.y;
        if (FOLD) sw += w;                   // lane-uniform, no reduction needed
    }

    if (FOLD) {
        int f0 = lid * 8;
        float4 sca = *reinterpret_cast<const float4*>(&g_scale[f0]);
        float4 scb = *reinterpret_cast<const float4*>(&g_scale[f0 + 4]);
        float4 sha = *reinterpret_cast<const float4*>(&g_shift[f0]);
        float4 shb = *reinterpret_cast<const float4*>(&g_shift[f0 + 4]);
        acc[0] = sca.x * acc[0] + sha.x * sw;
        acc[1] = sca.y * acc[1] + sha.y * sw;
        acc[2] = sca.z * acc[2] + sha.z * sw;
        acc[3] = sca.w * acc[3] + sha.w * sw;
        acc[4] = scb.x * acc[4] + shb.x * sw;
        acc[5] = scb.y * acc[5] + shb.y * sw;
        acc[6] = scb.z * acc[6] + shb.z * sw;
        acc[7] = scb.w * acc[7] + shb.w * sw;
    }

    uint4 o;
    *reinterpret_cast<__half2*>(&o.x) = __floats2half2_rn(acc[0], acc[1]);
    *reinterpret_cast<__half2*>(&o.y) = __floats2half2_rn(acc[2], acc[3]);
    *reinterpret_cast<__half2*>(&o.z) = __floats2half2_rn(acc[4], acc[5]);
    *reinterpret_cast<__half2*>(&o.w) = __floats2half2_rn(acc[6], acc[7]);
    *reinterpret_cast<uint4*>(&xout[node * FD2 + lid * 4]) = o;
}

// ------- fused tensor-core GEMM: C = prelu(A @ W^T + b), + BN stats --------
// A = g_hx1 [N,256] fp16 row-major.  W fp16 [256,256] row-major (= B col-major).
// USE_W1 selects the __device__ weight array; OUT_HALF -> g_hx0 else g_x0.
template <bool USE_W1, bool OUT_HALF>
__global__ __launch_bounds__(256) void k_gemm_tc(const float* __restrict__ bias,
                                                 const float* __restrict__ pw) {
    // smem: mainloop A/B tiles overlap epilogue C staging
    __shared__ __align__(16) unsigned char raw[GBM * LDC * 4 + 16 * GBN * 4];
    __half* As = reinterpret_cast<__half*>(raw);                 // [128][LDA]
    __half* Bs = reinterpret_cast<__half*>(raw + GBM * LDA * 2); // [64][LDA]
    float*  Cs = reinterpret_cast<float*>(raw);                  // [128][LDC]
    float(*Red)[GBN] = reinterpret_cast<float(*)[GBN]>(raw + GBM * LDC * 4);

    const __half* __restrict__ A  = reinterpret_cast<const __half*>(g_hx1);
    const __half* __restrict__ hW = USE_W1 ? g_hw1 : g_hw2;

    int bm = blockIdx.x * GBM;
    int bn = blockIdx.y * GBN;
    int t  = threadIdx.x;
    int wid = t >> 5;
    int wm  = wid >> 1;          // 0..3 : warp row (32 rows each)
    int wn  = wid & 1;           // 0..1 : warp col (32 cols each)

    // A loader: 128 rows x 64 halves; thread: row = t>>1, 32 halves at (t&1)*32
    int arow = t >> 1;
    int aseg = (t & 1) * 32;
    int gm_ld = bm + arow;
    // B loader: 64 rows(n) x 64 halves(k); thread: n = t>>2, 16 halves at (t&3)*16
    int brow = t >> 2;
    int bseg = (t & 3) * 16;

    wmma::fragment<wmma::accumulator, 16, 16, 16, float> c[2][2];
#pragma unroll
    for (int i = 0; i < 2; i++)
#pragma unroll
        for (int j = 0; j < 2; j++) wmma::fill_fragment(c[i][j], 0.0f);

    for (int k0 = 0; k0 < FDIM; k0 += GBK) {
        // load A tile (zero-fill OOB rows): 4x uint4 per thread
        uint4 a0 = make_uint4(0u,0u,0u,0u), a1 = a0, a2 = a0, a3 = a0;
        if (gm_ld < N_NODES) {
            const uint4* src = reinterpret_cast<const uint4*>(
                A + (size_t)gm_ld * FDIM + k0 + aseg);
            a0 = src[0]; a1 = src[1]; a2 = src[2]; a3 = src[3];
        }
        uint4* dstA = reinterpret_cast<uint4*>(&As[arow * LDA + aseg]);
        dstA[0] = a0; dstA[1] = a1; dstA[2] = a2; dstA[3] = a3;
        // load B tile (W rows bn..bn+63): 2x uint4 per thread
        const uint4* srcB = reinterpret_cast<const uint4*>(
            hW + (size_t)(bn + brow) * FDIM + k0 + bseg);
        uint4 b0 = srcB[0], b1 = srcB[1];
        uint4* dstB = reinterpret_cast<uint4*>(&Bs[brow * LDA + bseg]);
        dstB[0] = b0; dstB[1] = b1;
        __syncthreads();
#pragma unroll
        for (int kk = 0; kk < GBK; kk += 16) {
            wmma::fragment<wmma::matrix_a, 16, 16, 16, __half, wmma::row_major> af[2];
            wmma::fragment<wmma::matrix_b, 16, 16, 16, __half, wmma::col_major> bf[2];
#pragma unroll
            for (int i = 0; i < 2; i++)
                wmma::load_matrix_sync(af[i], &As[(wm * 32 + i * 16) * LDA + kk], LDA);
#pragma unroll
            for (int j = 0; j < 2; j++)
                wmma::load_matrix_sync(bf[j], &Bs[(wn * 32 + j * 16) * LDA + kk], LDA);
#pragma unroll
            for (int i = 0; i < 2; i++)
#pragma unroll
                for (int j = 0; j < 2; j++)
                    wmma::mma_sync(c[i][j], af[i], bf[j], c[i][j]);
        }
        __syncthreads();
    }

    // stage C to smem (overlaps As/Bs — separated by the final __syncthreads)
#pragma unroll
    for (int i = 0; i < 2; i++)
#pragma unroll
        for (int j = 0; j < 2; j++)
            wmma::store_matrix_sync(&Cs[(wm * 32 + i * 16) * LDC + wn * 32 + j * 16],
                                    c[i][j], LDC, wmma::mem_row_major);
    __syncthreads();

    // -------- epilogue: bias + PReLU + store + per-column partial stats ------
    int tn  = t & 15;          // 4-col group
    int tmg = t >> 4;          // 8-row group
    int n0 = bn + tn * 4;
    float4 bb  = *reinterpret_cast<const float4*>(&bias[n0]);
    float4 pwv = *reinterpret_cast<const float4*>(&pw[n0]);
    float cs[4]  = {0.f, 0.f, 0.f, 0.f};
    float cs2[4] = {0.f, 0.f, 0.f, 0.f};
#pragma unroll
    for (int r = 0; r < 8; r++) {
        int lr = tmg * 8 + r;
        int m  = bm + lr;
        float4 v = *reinterpret_cast<const float4*>(&Cs[lr * LDC + tn * 4]);
        v.x += bb.x; v.y += bb.y; v.z += bb.z; v.w += bb.w;
        v.x = (v.x >= 0.f) ? v.x : pwv.x * v.x;
        v.y = (v.y >= 0.f) ? v.y : pwv.y * v.y;
        v.z = (v.z >= 0.f) ? v.z : pwv.z * v.z;
        v.w = (v.w >= 0.f) ? v.w : pwv.w * v.w;
        if (m < N_NODES) {
            if (OUT_HALF) {
                __half2* dst = &g_hx0[m * FD2 + n0 / 2];
                dst[0] = __floats2half2_rn(v.x, v.y);
                dst[1] = __floats2half2_rn(v.z, v.w);
            } else {
                *reinterpret_cast<float4*>(&g_x0[(size_t)m * FDIM + n0]) = v;
            }
            cs[0] += v.x; cs[1] += v.y; cs[2] += v.z; cs[3] += v.w;
            cs2[0] += v.x * v.x; cs2[1] += v.y * v.y;
            cs2[2] += v.z * v.z; cs2[3] += v.w * v.w;
        }
    }

    // deterministic in-block column reduction (no atomics)
    int pbase = (blockIdx.y * GMB + blockIdx.x) * GBN;
#pragma unroll
    for (int i = 0; i < 4; i++) Red[tmg][tn * 4 + i] = cs[i];
    __syncthreads();
    if (t < GBN) {
        float s = 0.f;
#pragma unroll
        for (int r = 0; r < 16; r++) s += Red[r][t];
        g_gp1[pbase + t] = s;
    }
    __syncthreads();
#pragma unroll
    for (int i = 0; i < 4; i++) Red[tmg][tn * 4 + i] = cs2[i];
    __syncthreads();
    if (t < GBN) {
        float s = 0.f;
#pragma unroll
        for (int r = 0; r < 16; r++) s += Red[r][t];
        g_gp2[pbase + t] = s;
    }
}

// ------- BN finalize: 1024 threads, 4-way chunked, fixed combine order -----
__global__ void k_bn_finalize(const float* __restrict__ gamma,
                              const float* __restrict__ beta) {
    __shared__ float p1[4][FDIM];
    __shared__ float p2[4][FDIM];
    int f     = threadIdx.x & 255;
    int chunk = threadIdx.x >> 8;      // 0..3
    int by = f >> 6;
    int c  = f & 63;
    int bx0 = chunk * 59;
    int bx1 = (bx0 + 59 < GMB) ? bx0 + 59 : GMB;
    float s = 0.f, s2 = 0.f;
    for (int bx = bx0; bx < bx1; bx++) {
        int idx = (by * GMB + bx) * GBN + c;
        s  += g_gp1[idx];
        s2 += g_gp2[idx];
    }
    p1[chunk][f] = s;
    p2[chunk][f] = s2;
    __syncthreads();
    if (threadIdx.x < FDIM) {
        float S  = p1[0][f] + p1[1][f] + p1[2][f] + p1[3][f];   // fixed order
        float S2 = p2[0][f] + p2[1][f] + p2[2][f] + p2[3][f];
        float inv_n = 1.0f / (float)N_NODES;
        float mean = S * inv_n;
        float var  = S2 * inv_n - mean * mean;
        float sc   = gamma[f] * rsqrtf(var + BN_EPS);
        g_scale[f] = sc;
        g_shift[f] = beta[f] - mean * sc;
    }
}

// ---------------- final BN apply: g_x0 -> d_out ----------------
__global__ void k_bn_apply_out(float* __restrict__ out_ext) {
    int i = blockIdx.x * blockDim.x + threadIdx.x;
    if (i >= NF4) return;
    int f4 = (i & 63) << 2;
    float4 v  = reinterpret_cast<const float4*>(g_x0)[i];
    float4 sc = *reinterpret_cast<const float4*>(&g_scale[f4]);
    float4 sh = *reinterpret_cast<const float4*>(&g_shift[f4]);
    v.x = v.x * sc.x + sh.x;
    v.y = v.y * sc.y + sh.y;
    v.z = v.z * sc.z + sh.z;
    v.w = v.w * sc.w + sh.w;
    reinterpret_cast<float4*>(out_ext)[i] = v;
}

// ---------------- launch ----------------
extern "C" void kernel_launch(void* const* d_in, const int* in_sizes, int n_in,
                              void* d_out, int out_size) {
    const float* cell  = (const float*)d_in[0];
    const float* sub   = (const float*)d_in[1];
    const int*   ei    = (const int*)  d_in[2];
    const float* ew    = (const float*)d_in[3];
    const float* W1    = (const float*)d_in[4];
    const float* b1    = (const float*)d_in[5];
    const float* W2    = (const float*)d_in[6];
    const float* b2    = (const float*)d_in[7];
    const float* pw    = (const float*)d_in[8];
    const float* gamma = (const float*)d_in[9];
    const float* beta  = (const float*)d_in[10];
    float* out = (float*)d_out;

    const int T = 256;
    // graph normalization setup (recomputed each call — deterministic work)
    k_setup<<<(FDIM * FDIM + T - 1) / T, T>>>(W1, W2);  // packed init + W cvt
    k_concat<<<(NF4 + T - 1) / T, T>>>((const float4*)cell, (const float4*)sub);
    k_degree<<<(E_TOT + T - 1) / T, T>>>(ei, ew);
    k_scan_a<<<NBLK, 256>>>();             // dinv + local scan
    k_scan_b<<<1, 128>>>();                // scan block totals
    k_scan_c<<<NBLK, 256>>>();             // apply offsets -> colptr/cursor
    k_scatter<<<(E_TOT / 4 + T - 1) / T, T>>>(ei, ew);

    dim3 ggrid(GMB, FDIM / GBN);   // (235, 4)
    const int SG = N_NODES / 8;    // 3750 blocks, 8 warps = 8 nodes each

    // ---- layer 1 (fp16 hops) ----
    k_spmm<true , false><<<SG, 256>>>();        // hx0 -> hx1
    k_spmm<false, false><<<SG, 256>>>();        // hx1 -> hx0
    k_spmm<true , false><<<SG, 256>>>();        // hx0 -> hx1
    k_gemm_tc<true , true ><<<ggrid, T>>>(b1, pw);  // hx1 -> hx0 (fp16) + stats
    k_bn_finalize<<<1, 1024>>>(gamma, beta);

    // ---- layer 2 (hop 1 folds layer-1 BN via linearity) ----
    k_spmm<true , true ><<<SG, 256>>>();        // hx0 -> hx1 (BN folded)
    k_spmm<false, false><<<SG, 256>>>();        // hx1 -> hx0
    k_spmm<true , false><<<SG, 256>>>();        // hx0 -> hx1
    k_gemm_tc<false, false><<<ggrid, T>>>(b2, pw);  // hx1 -> g_x0 (fp32) + stats
    k_bn_finalize<<<1, 1024>>>(gamma, beta);
    k_bn_apply_out<<<(NF4 + T - 1) / T, T>>>(out);  // g_x0 -> d_out
}